// round 11
// baseline (speedup 1.0000x reference)
#include <cuda_runtime.h>
#include <cuda_bf16.h>
#include <cstdint>

// DGCNN forward.
//   edge_conv:  out[b,n,o] = lrelu( max_k ( u[b,idx_k,o] + t[b,n,o] ) )
//   u = (s*W_a)@x ; t = (s*(W_b-W_a))@x + (s*bias + bn_b)
// KNN inner GEMMs: exact fp32 SIMT, symmetric (lower triangle + mirror).
// u|t GEMMs (l2-l4) + conv5: bf16-split x3 mma.sync.
// conv5 split over K: first half overlapped with layer-4 KNN on side stream,
// second half fused with add + global max-pool.

#define B_   8
#define N_   1024
#define PTS  (B_ * N_)
#define KNN  20
#define NEG_INF __int_as_float(0xff800000)

__device__ static float          g_xc[PTS * 512];
__device__ static __nv_bfloat16  g_xch[PTS * 512];
__device__ static __nv_bfloat16  g_xcl[PTS * 512];
__device__ static float          g_inner[PTS * 1024];
__device__ static float          g_e[PTS * 1024];       // conv5 partial
__device__ static float          g_ut[PTS * 512];
__device__ static float          g_utw[512 * 128];
__device__ static __nv_bfloat16  g_utwh[512 * 128];
__device__ static __nv_bfloat16  g_utwl[512 * 128];
__device__ static __nv_bfloat16  g_c5h[1024 * 512];
__device__ static __nv_bfloat16  g_c5l[1024 * 512];
__device__ static float          g_tb[256];
__device__ static float          g_xx[PTS];
__device__ static int            g_idx[PTS * KNN];
__device__ static unsigned       g_pool[B_ * 1024];

__device__ __forceinline__ uint32_t smem_u32(const void* p) {
    uint32_t a;
    asm("{ .reg .u64 t; cvta.to.shared.u64 t, %1; cvt.u32.u64 %0, t; }"
        : "=r"(a) : "l"(p));
    return a;
}

__device__ __forceinline__ unsigned redux_max(unsigned v) {
    unsigned r;
    asm("redux.sync.max.u32 %0, %1, 0xffffffff;" : "=r"(r) : "r"(v));
    return r;
}

__device__ __forceinline__ unsigned fenc(float v) {
    unsigned u = __float_as_uint(v);
    return u ^ (((unsigned)((int)u >> 31)) | 0x80000000u);
}

#define LDSM_X4(r0, r1, r2, r3, addr) \
    asm volatile("ldmatrix.sync.aligned.m8n8.x4.shared.b16 {%0,%1,%2,%3}, [%4];" \
                 : "=r"(r0), "=r"(r1), "=r"(r2), "=r"(r3) : "r"(addr))

#define MMA_BF16(c, a, b0, b1) \
    asm volatile( \
        "mma.sync.aligned.m16n8k16.row.col.f32.bf16.bf16.f32 " \
        "{%0,%1,%2,%3}, {%4,%5,%6,%7}, {%8,%9}, {%0,%1,%2,%3};" \
        : "+f"((c)[0]), "+f"((c)[1]), "+f"((c)[2]), "+f"((c)[3]) \
        : "r"((a)[0]), "r"((a)[1]), "r"((a)[2]), "r"((a)[3]), \
          "r"(b0), "r"(b1))

// ---------------------------------------------------------------------------
// bf16-split mma.sync GEMM mainloop (shared)
// ---------------------------------------------------------------------------
#define SKA       40
#define TILE_B    (128 * SKA * 2)
#define STAGE_B   (4 * TILE_B)
#define MMA_SMEM  (2 * STAGE_B)
#define MMA_SMEM_POOL (2 * STAGE_B + 512)

struct MmaCtx {
    float acc[4][4][4];
    int m_warp, n_warp, lane;
};

__device__ __forceinline__ void mma_mainloop(
    char* smem, uint32_t sb0, MmaCtx& cx,
    const __nv_bfloat16* Ah, const __nv_bfloat16* Al, int lda, int m0,
    const __nv_bfloat16* Bh, const __nv_bfloat16* Bl, int ldb, int n0, int K)
{
    const int tid  = threadIdx.x;
    const int wid  = tid >> 5;
    const int lane = tid & 31;
    cx.lane = lane;
    cx.m_warp = (wid & 1) * 64;
    cx.n_warp = (wid >> 1) * 32;

    #pragma unroll
    for (int i = 0; i < 4; i++)
        #pragma unroll
        for (int j = 0; j < 4; j++)
            #pragma unroll
            for (int q = 0; q < 4; q++) cx.acc[i][j][q] = 0.f;

    uint4 stg[8];
    auto ldG = [&](int kc) {
        #pragma unroll
        for (int i = 0; i < 8; i++) {
            int u = tid + i * 256;
            int tile = u >> 9;
            int r = (u >> 2) & 127;
            int q = u & 3;
            const __nv_bfloat16* src;
            int ld_, r0;
            if (tile == 0)      { src = Ah; ld_ = lda; r0 = m0; }
            else if (tile == 1) { src = Al; ld_ = lda; r0 = m0; }
            else if (tile == 2) { src = Bh; ld_ = ldb; r0 = n0; }
            else                { src = Bl; ld_ = ldb; r0 = n0; }
            stg[i] = *reinterpret_cast<const uint4*>(
                src + (size_t)(r0 + r) * ld_ + kc + q * 8);
        }
    };
    auto stS = [&](int stage) {
        char* base = smem + stage * STAGE_B;
        #pragma unroll
        for (int i = 0; i < 8; i++) {
            int u = tid + i * 256;
            int tile = u >> 9;
            int r = (u >> 2) & 127;
            int q = u & 3;
            *reinterpret_cast<uint4*>(base + tile * TILE_B + r * (SKA * 2) + q * 16) = stg[i];
        }
    };

    const int nc = K >> 5;
    ldG(0); stS(0);
    __syncthreads();

    for (int c = 0; c < nc; c++) {
        int buf = c & 1;
        if (c + 1 < nc) ldG((c + 1) * 32);

        const uint32_t sb = sb0 + buf * STAGE_B;
        #pragma unroll
        for (int ks = 0; ks < 32; ks += 16) {
            uint32_t ah[4][4], al[4][4], bh[2][4], bl[2][4];
            const uint32_t lrow = (lane & 15);
            const uint32_t lcol = (lane >> 4) * 8;
            #pragma unroll
            for (int mt = 0; mt < 4; mt++) {
                uint32_t off = ((cx.m_warp + mt * 16 + lrow) * SKA + ks + lcol) * 2;
                LDSM_X4(ah[mt][0], ah[mt][1], ah[mt][2], ah[mt][3], sb + off);
                LDSM_X4(al[mt][0], al[mt][1], al[mt][2], al[mt][3], sb + TILE_B + off);
            }
            #pragma unroll
            for (int np = 0; np < 2; np++) {
                uint32_t off = ((cx.n_warp + np * 16 + lrow) * SKA + ks + lcol) * 2;
                LDSM_X4(bh[np][0], bh[np][1], bh[np][2], bh[np][3], sb + 2 * TILE_B + off);
                LDSM_X4(bl[np][0], bl[np][1], bl[np][2], bl[np][3], sb + 3 * TILE_B + off);
            }
            #pragma unroll
            for (int mt = 0; mt < 4; mt++)
                #pragma unroll
                for (int nt = 0; nt < 4; nt++) {
                    int np = nt >> 1, half = nt & 1;
                    MMA_BF16(cx.acc[mt][nt], ah[mt], bh[np][half], bh[np][2 + half]);
                    MMA_BF16(cx.acc[mt][nt], ah[mt], bl[np][half], bl[np][2 + half]);
                    MMA_BF16(cx.acc[mt][nt], al[mt], bh[np][half], bh[np][2 + half]);
                }
        }

        if (c + 1 < nc) stS(buf ^ 1);
        __syncthreads();
    }
}

__global__ void __launch_bounds__(256)
mma_gemm(const __nv_bfloat16* __restrict__ Ah, const __nv_bfloat16* __restrict__ Al,
         int lda, long long sA,
         const __nv_bfloat16* __restrict__ Bh, const __nv_bfloat16* __restrict__ Bl,
         int ldb, long long sB,
         float* __restrict__ C, int ldc, long long sC, int K)
{
    extern __shared__ char smem[];
    const uint32_t sb0 = smem_u32(smem);
    const int bz = blockIdx.z;
    Ah += bz * sA; Al += bz * sA; Bh += bz * sB; Bl += bz * sB; C += bz * sC;
    const int m0 = blockIdx.y * 128;
    const int n0 = blockIdx.x * 128;

    MmaCtx cx;
    mma_mainloop(smem, sb0, cx, Ah, Al, lda, m0, Bh, Bl, ldb, n0, K);

    #pragma unroll
    for (int mt = 0; mt < 4; mt++)
        #pragma unroll
        for (int nt = 0; nt < 4; nt++) {
            int rm = m0 + cx.m_warp + mt * 16 + (cx.lane >> 2);
            int cn = n0 + cx.n_warp + nt * 8 + (cx.lane & 3) * 2;
            *reinterpret_cast<float2*>(&C[(size_t)rm * ldc + cn]) =
                make_float2(cx.acc[mt][nt][0], cx.acc[mt][nt][1]);
            *reinterpret_cast<float2*>(&C[(size_t)(rm + 8) * ldc + cn]) =
                make_float2(cx.acc[mt][nt][2], cx.acc[mt][nt][3]);
        }
}

// conv5 second half: accumulate + partial-e add + row-max reduce -> pool.
__global__ void __launch_bounds__(256)
mma_gemm_pool_add(const __nv_bfloat16* __restrict__ Ah,
                  const __nv_bfloat16* __restrict__ Al, int lda,
                  const __nv_bfloat16* __restrict__ Bh,
                  const __nv_bfloat16* __restrict__ Bl, int ldb,
                  const float* __restrict__ e, int lde,
                  unsigned* __restrict__ pool, int K)
{
    extern __shared__ char smem[];
    const uint32_t sb0 = smem_u32(smem);
    unsigned* spool = reinterpret_cast<unsigned*>(smem + 2 * STAGE_B);
    const int tid = threadIdx.x;
    if (tid < 128) spool[tid] = 0u;

    const int m0 = blockIdx.y * 128;
    const int n0 = blockIdx.x * 128;
    const int b  = m0 >> 10;

    MmaCtx cx;
    mma_mainloop(smem, sb0, cx, Ah, Al, lda, m0, Bh, Bl, ldb, n0, K);

    #pragma unroll
    for (int mt = 0; mt < 4; mt++)
        #pragma unroll
        for (int nt = 0; nt < 4; nt++) {
            int rm = m0 + cx.m_warp + mt * 16 + (cx.lane >> 2);
            int cn = n0 + cx.n_warp + nt * 8 + (cx.lane & 3) * 2;
            float2 e0 = *reinterpret_cast<const float2*>(&e[(size_t)rm * lde + cn]);
            float2 e1 = *reinterpret_cast<const float2*>(&e[(size_t)(rm + 8) * lde + cn]);
            cx.acc[mt][nt][0] += e0.x; cx.acc[mt][nt][1] += e0.y;
            cx.acc[mt][nt][2] += e1.x; cx.acc[mt][nt][3] += e1.y;
        }

    #pragma unroll
    for (int nt = 0; nt < 4; nt++)
        #pragma unroll
        for (int j = 0; j < 2; j++) {
            float v = NEG_INF;
            #pragma unroll
            for (int mt = 0; mt < 4; mt++)
                v = fmaxf(v, fmaxf(cx.acc[mt][nt][j], cx.acc[mt][nt][2 + j]));
            v = fmaxf(v, __shfl_xor_sync(0xffffffffu, v, 4));
            v = fmaxf(v, __shfl_xor_sync(0xffffffffu, v, 8));
            v = fmaxf(v, __shfl_xor_sync(0xffffffffu, v, 16));
            if ((cx.lane >> 2) == 0) {
                unsigned uu = __float_as_uint(v);
                uu = (uu >> 31) ? ~uu : (uu | 0x80000000u);
                atomicMax(&spool[cx.n_warp + nt * 8 + (cx.lane & 3) * 2 + j], uu);
            }
        }
    __syncthreads();
    if (tid < 128) atomicMax(&pool[b * 1024 + n0 + tid], spool[tid]);
}

// ---------------------------------------------------------------------------
// fp32 SIMT GEMM machinery (exact path)
// ---------------------------------------------------------------------------
#define FMA_F32X2(d, a, b, c) \
    asm("fma.rn.f32x2 %0, %1, %2, %3;" : "=l"(d) : "l"(a), "l"(b), "l"(c))
__device__ __forceinline__ float f2lo(unsigned long long v) {
    return __uint_as_float((unsigned)(v & 0xffffffffull));
}
__device__ __forceinline__ float f2hi(unsigned long long v) {
    return __uint_as_float((unsigned)(v >> 32));
}

template<int BM, int BN, int TH>
__global__ void __launch_bounds__(TH, 2)
gemm_f2(const float* __restrict__ A, int lda, long long sA,
        const float* __restrict__ B, int ldb, long long sB,
        float* __restrict__ C, int ldc, long long sC, int K)
{
    constexpr int BK = 8;
    constexpr int LA = 2 * BM + 4;
    constexpr int LB = BN + 4;
    constexpr int NX = BN / 8;
    constexpr int NY = BM / 8;
    static_assert(NX * NY == TH, "threads");
    constexpr int CA = (BM * 2) / TH;
    constexpr int CB = (BN * 2) / TH;

    __shared__ float As2[2][BK][LA];
    __shared__ float Bs[2][BK][LB];

    const int bz = blockIdx.z;
    A += bz * sA; B += bz * sB; C += bz * sC;
    const int m0 = blockIdx.y * BM;
    const int n0 = blockIdx.x * BN;
    const int tid = threadIdx.x;
    const int tx = tid % NX;
    const int ty = tid / NX;
    const bool a4 = ((lda & 3) == 0);
    const bool b4 = ((ldb & 3) == 0);

    unsigned long long acc[8][4];
    #pragma unroll
    for (int i = 0; i < 8; i++)
        #pragma unroll
        for (int j = 0; j < 4; j++) acc[i][j] = 0ull;

    float4 stA[CA], stB[CB];
    auto ldGA = [&](int k0) {
        #pragma unroll
        for (int i = 0; i < CA; i++) {
            int f4 = tid + i * TH;
            int row = f4 >> 1, kq = (f4 & 1) << 2;
            int k = k0 + kq;
            const float* p = A + (size_t)(m0 + row) * lda;
            float4 v;
            if (a4 && (k + 3) < K) v = *reinterpret_cast<const float4*>(p + k);
            else {
                v.x = (k     < K) ? p[k]     : 0.f;
                v.y = (k + 1 < K) ? p[k + 1] : 0.f;
                v.z = (k + 2 < K) ? p[k + 2] : 0.f;
                v.w = (k + 3 < K) ? p[k + 3] : 0.f;
            }
            stA[i] = v;
        }
    };
    auto ldGB = [&](int k0) {
        #pragma unroll
        for (int i = 0; i < CB; i++) {
            int f4 = tid + i * TH;
            int row = f4 >> 1, kq = (f4 & 1) << 2;
            int k = k0 + kq;
            const float* p = B + (size_t)(n0 + row) * ldb;
            float4 v;
            if (b4 && (k + 3) < K) v = *reinterpret_cast<const float4*>(p + k);
            else {
                v.x = (k     < K) ? p[k]     : 0.f;
                v.y = (k + 1 < K) ? p[k + 1] : 0.f;
                v.z = (k + 2 < K) ? p[k + 2] : 0.f;
                v.w = (k + 3 < K) ? p[k + 3] : 0.f;
            }
            stB[i] = v;
        }
    };
    auto stS = [&](int buf) {
        #pragma unroll
        for (int i = 0; i < CA; i++) {
            int f4 = tid + i * TH;
            int row = f4 >> 1, kq = (f4 & 1) << 2;
            float vv[4] = {stA[i].x, stA[i].y, stA[i].z, stA[i].w};
            #pragma unroll
            for (int j = 0; j < 4; j++)
                *reinterpret_cast<float2*>(&As2[buf][kq + j][2 * row]) =
                    make_float2(vv[j], vv[j]);
        }
        #pragma unroll
        for (int i = 0; i < CB; i++) {
            int f4 = tid + i * TH;
            int row = f4 >> 1, kq = (f4 & 1) << 2;
            Bs[buf][kq + 0][row] = stB[i].x;
            Bs[buf][kq + 1][row] = stB[i].y;
            Bs[buf][kq + 2][row] = stB[i].z;
            Bs[buf][kq + 3][row] = stB[i].w;
        }
    };

    const int nt = (K + BK - 1) / BK;
    ldGA(0); ldGB(0); stS(0);
    __syncthreads();

    for (int t = 0; t < nt; t++) {
        int buf = t & 1;
        if (t + 1 < nt) { ldGA((t + 1) * BK); ldGB((t + 1) * BK); }
        #pragma unroll
        for (int k = 0; k < BK; k++) {
            ulonglong2 a01 = *reinterpret_cast<const ulonglong2*>(&As2[buf][k][2 * (ty * 4)]);
            ulonglong2 a23 = *reinterpret_cast<const ulonglong2*>(&As2[buf][k][2 * (ty * 4) + 4]);
            ulonglong2 a45 = *reinterpret_cast<const ulonglong2*>(&As2[buf][k][2 * (BM / 2 + ty * 4)]);
            ulonglong2 a67 = *reinterpret_cast<const ulonglong2*>(&As2[buf][k][2 * (BM / 2 + ty * 4) + 4]);
            ulonglong2 b01 = *reinterpret_cast<const ulonglong2*>(&Bs[buf][k][tx * 4]);
            ulonglong2 b23 = *reinterpret_cast<const ulonglong2*>(&Bs[buf][k][BN / 2 + tx * 4]);
            unsigned long long av[8] = {a01.x, a01.y, a23.x, a23.y,
                                        a45.x, a45.y, a67.x, a67.y};
            unsigned long long bv[4] = {b01.x, b01.y, b23.x, b23.y};
            #pragma unroll
            for (int i = 0; i < 8; i++)
                #pragma unroll
                for (int j = 0; j < 4; j++)
                    FMA_F32X2(acc[i][j], av[i], bv[j], acc[i][j]);
        }
        if (t + 1 < nt) stS(buf ^ 1);
        __syncthreads();
    }

    #pragma unroll
    for (int i = 0; i < 8; i++) {
        int m = m0 + ((i < 4) ? (ty * 4 + i) : (BM / 2 + ty * 4 + i - 4));
        float4 o0, o1;
        o0.x = f2lo(acc[i][0]); o0.y = f2hi(acc[i][0]);
        o0.z = f2lo(acc[i][1]); o0.w = f2hi(acc[i][1]);
        o1.x = f2lo(acc[i][2]); o1.y = f2hi(acc[i][2]);
        o1.z = f2lo(acc[i][3]); o1.w = f2hi(acc[i][3]);
        *reinterpret_cast<float4*>(&C[(size_t)m * ldc + n0 + tx * 4]) = o0;
        *reinterpret_cast<float4*>(&C[(size_t)m * ldc + n0 + BN / 2 + tx * 4]) = o1;
    }
}

// ---------------------------------------------------------------------------
// Symmetric fp32 GEMM: C = X.X^T per batch (lower triangle + mirror store).
// ---------------------------------------------------------------------------
__global__ void __launch_bounds__(256, 2)
gemm_sym(const float* __restrict__ X, int lda, long long sX,
         float* __restrict__ C, int ldc, long long sC, int K)
{
    constexpr int BM = 128, BN = 128, BK = 8;
    constexpr int LA = 2 * BM + 4;
    constexpr int LB = BN + 4;
    constexpr int NX = BN / 8;

    __shared__ float As2[2][BK][LA];
    __shared__ float Bs[2][BK][LB];

    int t = blockIdx.x;
    int i_ = (int)((sqrtf(8.f * t + 1.f) - 1.f) * 0.5f);
    while ((i_ + 1) * (i_ + 2) / 2 <= t) i_++;
    while (i_ * (i_ + 1) / 2 > t) i_--;
    int j_ = t - i_ * (i_ + 1) / 2;

    const int bz = blockIdx.z;
    const float* A = X + bz * sX;
    float* Cb = C + bz * sC;
    const int m0 = i_ * BM;
    const int n0 = j_ * BN;
    const int tid = threadIdx.x;
    const int tx = tid % NX;
    const int ty = tid / NX;
    const bool a4 = ((lda & 3) == 0);

    unsigned long long acc[8][4];
    #pragma unroll
    for (int i = 0; i < 8; i++)
        #pragma unroll
        for (int j = 0; j < 4; j++) acc[i][j] = 0ull;

    float4 stA[1], stB[1];
    auto ldGA = [&](int k0) {
        int row = tid >> 1, kq = (tid & 1) << 2;
        int k = k0 + kq;
        const float* p = A + (size_t)(m0 + row) * lda;
        float4 v;
        if (a4 && (k + 3) < K) v = *reinterpret_cast<const float4*>(p + k);
        else {
            v.x = (k     < K) ? p[k]     : 0.f;
            v.y = (k + 1 < K) ? p[k + 1] : 0.f;
            v.z = (k + 2 < K) ? p[k + 2] : 0.f;
            v.w = (k + 3 < K) ? p[k + 3] : 0.f;
        }
        stA[0] = v;
    };
    auto ldGB = [&](int k0) {
        int row = tid >> 1, kq = (tid & 1) << 2;
        int k = k0 + kq;
        const float* p = A + (size_t)(n0 + row) * lda;
        float4 v;
        if (a4 && (k + 3) < K) v = *reinterpret_cast<const float4*>(p + k);
        else {
            v.x = (k     < K) ? p[k]     : 0.f;
            v.y = (k + 1 < K) ? p[k + 1] : 0.f;
            v.z = (k + 2 < K) ? p[k + 2] : 0.f;
            v.w = (k + 3 < K) ? p[k + 3] : 0.f;
        }
        stB[0] = v;
    };
    auto stS = [&](int buf) {
        int row = tid >> 1, kq = (tid & 1) << 2;
        float vv[4] = {stA[0].x, stA[0].y, stA[0].z, stA[0].w};
        #pragma unroll
        for (int j = 0; j < 4; j++)
            *reinterpret_cast<float2*>(&As2[buf][kq + j][2 * row]) =
                make_float2(vv[j], vv[j]);
        Bs[buf][kq + 0][row] = stB[0].x;
        Bs[buf][kq + 1][row] = stB[0].y;
        Bs[buf][kq + 2][row] = stB[0].z;
        Bs[buf][kq + 3][row] = stB[0].w;
    };

    const int nt = (K + BK - 1) / BK;
    ldGA(0); ldGB(0); stS(0);
    __syncthreads();

    for (int tt = 0; tt < nt; tt++) {
        int buf = tt & 1;
        if (tt + 1 < nt) { ldGA((tt + 1) * BK); ldGB((tt + 1) * BK); }
        #pragma unroll
        for (int k = 0; k < BK; k++) {
            ulonglong2 a01 = *reinterpret_cast<const ulonglong2*>(&As2[buf][k][2 * (ty * 4)]);
            ulonglong2 a23 = *reinterpret_cast<const ulonglong2*>(&As2[buf][k][2 * (ty * 4) + 4]);
            ulonglong2 a45 = *reinterpret_cast<const ulonglong2*>(&As2[buf][k][2 * (BM / 2 + ty * 4)]);
            ulonglong2 a67 = *reinterpret_cast<const ulonglong2*>(&As2[buf][k][2 * (BM / 2 + ty * 4) + 4]);
            ulonglong2 b01 = *reinterpret_cast<const ulonglong2*>(&Bs[buf][k][tx * 4]);
            ulonglong2 b23 = *reinterpret_cast<const ulonglong2*>(&Bs[buf][k][BN / 2 + tx * 4]);
            unsigned long long av[8] = {a01.x, a01.y, a23.x, a23.y,
                                        a45.x, a45.y, a67.x, a67.y};
            unsigned long long bv[4] = {b01.x, b01.y, b23.x, b23.y};
            #pragma unroll
            for (int i = 0; i < 8; i++)
                #pragma unroll
                for (int j = 0; j < 4; j++)
                    FMA_F32X2(acc[i][j], av[i], bv[j], acc[i][j]);
        }
        if (tt + 1 < nt) stS(buf ^ 1);
        __syncthreads();
    }

    float f[8][8];
    int mrow[8], ncol[8];
    #pragma unroll
    for (int i = 0; i < 8; i++) {
        mrow[i] = m0 + ((i < 4) ? (ty * 4 + i) : (64 + ty * 4 + i - 4));
        ncol[i] = n0 + ((i < 4) ? (tx * 4 + i) : (64 + tx * 4 + i - 4));
        f[i][0] = f2lo(acc[i][0]); f[i][1] = f2hi(acc[i][0]);
        f[i][2] = f2lo(acc[i][1]); f[i][3] = f2hi(acc[i][1]);
        f[i][4] = f2lo(acc[i][2]); f[i][5] = f2hi(acc[i][2]);
        f[i][6] = f2lo(acc[i][3]); f[i][7] = f2hi(acc[i][3]);
    }

    #pragma unroll
    for (int i = 0; i < 8; i++) {
        *reinterpret_cast<float4*>(&Cb[(size_t)mrow[i] * ldc + ncol[0]]) =
            make_float4(f[i][0], f[i][1], f[i][2], f[i][3]);
        *reinterpret_cast<float4*>(&Cb[(size_t)mrow[i] * ldc + ncol[4]]) =
            make_float4(f[i][4], f[i][5], f[i][6], f[i][7]);
    }
    if (i_ != j_) {
        #pragma unroll
        for (int q = 0; q < 8; q++) {
            *reinterpret_cast<float4*>(&Cb[(size_t)ncol[q] * ldc + mrow[0]]) =
                make_float4(f[0][q], f[1][q], f[2][q], f[3][q]);
            *reinterpret_cast<float4*>(&Cb[(size_t)ncol[q] * ldc + mrow[4]]) =
                make_float4(f[4][q], f[5][q], f[6][q], f[7][q]);
        }
    }
}

// ---------------------------------------------------------------------------
__global__ void diag_xx(const float* __restrict__ inner, float* __restrict__ xx)
{
    int p = blockIdx.x * 256 + threadIdx.x;
    if (p < PTS) xx[p] = inner[(size_t)p * N_ + (p & (N_ - 1))];
}

// ---------------------------------------------------------------------------
// top-20: warp per row, float4 scan, u32 key top-2 cache + index regs,
// pops via redux.sync.max.u32 pair.
// ---------------------------------------------------------------------------
__device__ __forceinline__ void tk_upd(unsigned& k1, unsigned& m1,
                                       unsigned& k2, unsigned& m2,
                                       unsigned e, unsigned m) {
    if (e > k1)      { k2 = k1; m2 = m1; k1 = e; m1 = m; }
    else if (e > k2) { k2 = e; m2 = m; }
}

__global__ void __launch_bounds__(256)
topk_kernel(const float* __restrict__ inner, const float* __restrict__ xx,
            int* __restrict__ idx_out)
{
    __shared__ uint4 s4[8][N_ / 4];
    int wid  = threadIdx.x >> 5;
    int lane = threadIdx.x & 31;
    int row  = blockIdx.x * 8 + wid;
    int b    = row >> 10;
    uint4* sw4 = s4[wid];
    unsigned* sw = reinterpret_cast<unsigned*>(sw4);
    const float4* r4 = reinterpret_cast<const float4*>(inner + (size_t)row * N_);
    const float4* x4 = reinterpret_cast<const float4*>(xx + (b << 10));

    unsigned k1 = 0, m1 = 0, k2 = 0, m2 = 0;
    #pragma unroll
    for (int i = 0; i < 8; i++) {
        int q = i * 32 + lane;
        float4 rv = r4[q];
        float4 xv = x4[q];
        unsigned mb = (unsigned)q * 4;
        unsigned e0 = fenc(fmaf(2.f, rv.x, -xv.x));
        unsigned e1 = fenc(fmaf(2.f, rv.y, -xv.y));
        unsigned e2 = fenc(fmaf(2.f, rv.z, -xv.z));
        unsigned e3 = fenc(fmaf(2.f, rv.w, -xv.w));
        sw4[q] = make_uint4(e0, e1, e2, e3);
        tk_upd(k1, m1, k2, m2, e0, mb);
        tk_upd(k1, m1, k2, m2, e1, mb + 1);
        tk_upd(k1, m1, k2, m2, e2, mb + 2);
        tk_upd(k1, m1, k2, m2, e3, mb + 3);
    }
    __syncwarp();

    for (int it = 0; it < KNN; it++) {
        unsigned wkey = redux_max(k1);
        unsigned cand = (k1 == wkey) ? (1023u - m1) : 0u;
        unsigned widx = redux_max(cand);
        unsigned m = 1023u - widx;
        if (lane == 0) idx_out[row * KNN + it] = (int)m;
        if (k1 == wkey && (1023u - m1) == widx) {
            sw[m] = 0;
            k1 = k2; m1 = m2; k2 = 0; m2 = 0;
            if (k1 == 0) {
                #pragma unroll
                for (int i = 0; i < 8; i++) {
                    int q = i * 32 + lane;
                    uint4 v = sw4[q];
                    unsigned mb = (unsigned)q * 4;
                    tk_upd(k1, m1, k2, m2, v.x, mb);
                    tk_upd(k1, m1, k2, m2, v.y, mb + 1);
                    tk_upd(k1, m1, k2, m2, v.z, mb + 2);
                    tk_upd(k1, m1, k2, m2, v.w, mb + 3);
                }
            }
        }
        __syncwarp();
    }
}

// ---------------------------------------------------------------------------
__device__ __forceinline__ void split_store(float v, __nv_bfloat16* h, __nv_bfloat16* l,
                                            size_t i)
{
    __nv_bfloat16 hb = __float2bfloat16(v);
    h[i] = hb;
    l[i] = __float2bfloat16(v - __bfloat162float(hb));
}

__global__ void prep_w(const float* __restrict__ W, int C, int O,
                       const float* __restrict__ bias,
                       const float* __restrict__ bng, const float* __restrict__ bnb,
                       float* __restrict__ utw,
                       __nv_bfloat16* __restrict__ utwh, __nv_bfloat16* __restrict__ utwl,
                       float* __restrict__ tb)
{
    const float inv = 1.0f / sqrtf(1.00001f);
    int i = blockIdx.x * 256 + threadIdx.x;
    if (i < O * C) {
        int o = i / C, c = i - o * C;
        float s = bng[o] * inv;
        float wa = W[o * 2 * C + c];
        float wb = W[o * 2 * C + C + c];
        float vu = s * wa;
        float vt = s * (wb - wa);
        utw[(size_t)o * C + c] = vu;
        utw[(size_t)(O + o) * C + c] = vt;
        split_store(vu, utwh, utwl, (size_t)o * C + c);
        split_store(vt, utwh, utwl, (size_t)(O + o) * C + c);
    }
    if (i < O) {
        float s = bng[i] * inv;
        tb[i] = s * (bias ? bias[i] : 0.f) + bnb[i];
    }
}

__global__ void prep_c5(const float* __restrict__ W,
                        __nv_bfloat16* __restrict__ h, __nv_bfloat16* __restrict__ l)
{
    int i = blockIdx.x * 256 + threadIdx.x;
    if (i < 1024 * 512) split_store(W[i], h, l, i);
}

// ---------------------------------------------------------------------------
__global__ void gathermax(const float* __restrict__ ut, const float* __restrict__ tb,
                          const int* __restrict__ idx,
                          float* __restrict__ xc,
                          __nv_bfloat16* __restrict__ xch, __nv_bfloat16* __restrict__ xcl,
                          int colOff, int CO)
{
    __shared__ int sidx[16][KNN];
    int ty = threadIdx.y, tx = threadIdx.x;
    int p = blockIdx.x * blockDim.y + ty;
    int b = p >> 10;
    for (int k = tx; k < KNN; k += blockDim.x) sidx[ty][k] = idx[p * KNN + k];
    __syncthreads();

    int st = 2 * CO;
    float4 tv = *reinterpret_cast<const float4*>(ut + (size_t)p * st + CO + tx * 4);
    float4 bv = *reinterpret_cast<const float4*>(tb + tx * 4);
    tv.x += bv.x; tv.y += bv.y; tv.z += bv.z; tv.w += bv.w;

    float4 mx = make_float4(NEG_INF, NEG_INF, NEG_INF, NEG_INF);
    #pragma unroll 4
    for (int k = 0; k < KNN; k++) {
        int j = sidx[ty][k];
        float4 v = *reinterpret_cast<const float4*>(
            ut + (size_t)((b << 10) + j) * st + tx * 4);
        mx.x = fmaxf(mx.x, v.x + tv.x);
        mx.y = fmaxf(mx.y, v.y + tv.y);
        mx.z = fmaxf(mx.z, v.z + tv.z);
        mx.w = fmaxf(mx.w, v.w + tv.w);
    }
    mx.x = (mx.x >= 0.f) ? mx.x : 0.01f * mx.x;
    mx.y = (mx.y >= 0.f) ? mx.y : 0.01f * mx.y;
    mx.z = (mx.z >= 0.f) ? mx.z : 0.01f * mx.z;
    mx.w = (mx.w >= 0.f) ? mx.w : 0.01f * mx.w;

    size_t o = (size_t)p * 512 + colOff + tx * 4;
    *reinterpret_cast<float4*>(xc + o) = mx;

    float vals[4] = {mx.x, mx.y, mx.z, mx.w};
    __nv_bfloat16 hb[4], lb[4];
    #pragma unroll
    for (int i = 0; i < 4; i++) {
        hb[i] = __float2bfloat16(vals[i]);
        lb[i] = __float2bfloat16(vals[i] - __bfloat162float(hb[i]));
    }
    *reinterpret_cast<uint2*>(xch + o) = *reinterpret_cast<uint2*>(hb);
    *reinterpret_cast<uint2*>(xcl + o) = *reinterpret_cast<uint2*>(lb);
}

// ---------------------------------------------------------------------------
__global__ void zero_pool(unsigned* pool)
{
    int i = blockIdx.x * 256 + threadIdx.x;
    if (i < B_ * 1024) pool[i] = 0u;
}

__device__ __forceinline__ float dec_pool(unsigned u)
{
    return (u & 0x80000000u) ? __uint_as_float(u & 0x7fffffffu) : __uint_as_float(~u);
}

// ---------------------------------------------------------------------------
// fused MLP head: block per batch, warp-per-output (same reduction order as
// the previous 3 kernels -> bit-identical).
// ---------------------------------------------------------------------------
__global__ void __launch_bounds__(512)
mlp_head(const unsigned* __restrict__ pool,
         const float* __restrict__ w1, const float* __restrict__ g6,
         const float* __restrict__ b6,
         const float* __restrict__ w2, const float* __restrict__ wb2,
         const float* __restrict__ g7, const float* __restrict__ b7,
         const float* __restrict__ w3, const float* __restrict__ wb3,
         float* __restrict__ out)
{
    __shared__ float sp[1024];
    __shared__ float sy1[512];
    __shared__ float sy2[256];
    const int b = blockIdx.x;
    const int tid = threadIdx.x;
    const int wid = tid >> 5, lane = tid & 31;
    const float inv = 1.0f / sqrtf(1.00001f);

    for (int i = tid; i < 1024; i += 512) sp[i] = dec_pool(pool[b * 1024 + i]);
    __syncthreads();

    for (int j = wid; j < 512; j += 16) {
        const float* wr = w1 + (size_t)j * 1024;
        float s = 0.f;
        for (int c = lane; c < 1024; c += 32) s += sp[c] * wr[c];
        #pragma unroll
        for (int off = 16; off; off >>= 1) s += __shfl_xor_sync(0xffffffffu, s, off);
        if (lane == 0) {
            float v = s * (g6[j] * inv) + b6[j];
            sy1[j] = (v >= 0.f) ? v : 0.01f * v;
        }
    }
    __syncthreads();

    for (int j = wid; j < 256; j += 16) {
        const float* wr = w2 + (size_t)j * 512;
        float s = 0.f;
        for (int c = lane; c < 512; c += 32) s += sy1[c] * wr[c];
        #pragma unroll
        for (int off = 16; off; off >>= 1) s += __shfl_xor_sync(0xffffffffu, s, off);
        if (lane == 0) {
            float v = (s + wb2[j]) * (g7[j] * inv) + b7[j];
            sy2[j] = (v >= 0.f) ? v : 0.01f * v;
        }
    }
    __syncthreads();

    for (int j = wid; j < 40; j += 16) {
        const float* wr = w3 + (size_t)j * 256;
        float s = 0.f;
        for (int c = lane; c < 256; c += 32) s += sy2[c] * wr[c];
        #pragma unroll
        for (int off = 16; off; off >>= 1) s += __shfl_xor_sync(0xffffffffu, s, off);
        if (lane == 0) out[b * 40 + j] = s + wb3[j];
    }
}

// ---------------------------------------------------------------------------
extern "C" void kernel_launch(void* const* d_in, const int* in_sizes, int n_in,
                              void* d_out, int out_size)
{
    const float* x        = (const float*)d_in[0];
    const float* conv1_w  = (const float*)d_in[1];
    const float* conv1_b  = (const float*)d_in[2];
    const float* bn1_g    = (const float*)d_in[3];
    const float* bn1_b    = (const float*)d_in[4];
    const float* conv2_w  = (const float*)d_in[5];
    const float* bn2_g    = (const float*)d_in[6];
    const float* bn2_b    = (const float*)d_in[7];
    const float* conv3_w  = (const float*)d_in[8];
    const float* bn3_g    = (const float*)d_in[9];
    const float* bn3_b    = (const float*)d_in[10];
    const float* conv4_w  = (const float*)d_in[11];
    const float* bn4_g    = (const float*)d_in[12];
    const float* bn4_b    = (const float*)d_in[13];
    const float* conv5_w  = (const float*)d_in[14];
    const float* lin1_w   = (const float*)d_in[15];
    const float* bn6_g    = (const float*)d_in[16];
    const float* bn6_b    = (const float*)d_in[17];
    const float* lin2_w   = (const float*)d_in[18];
    const float* lin2_b   = (const float*)d_in[19];
    const float* bn7_g    = (const float*)d_in[20];
    const float* bn7_b    = (const float*)d_in[21];
    const float* lin3_w   = (const float*)d_in[22];
    const float* lin3_b   = (const float*)d_in[23];

    float *xc, *inner, *e, *ut, *utw, *tb, *xxp;
    __nv_bfloat16 *xch, *xcl, *utwh, *utwl, *c5h, *c5l;
    int* idx; unsigned* pool;
    cudaGetSymbolAddress((void**)&xc,    g_xc);
    cudaGetSymbolAddress((void**)&inner, g_inner);
    cudaGetSymbolAddress((void**)&e,     g_e);
    cudaGetSymbolAddress((void**)&xch,   g_xch);
    cudaGetSymbolAddress((void**)&xcl,   g_xcl);
    cudaGetSymbolAddress((void**)&ut,    g_ut);
    cudaGetSymbolAddress((void**)&utw,   g_utw);
    cudaGetSymbolAddress((void**)&utwh,  g_utwh);
    cudaGetSymbolAddress((void**)&utwl,  g_utwl);
    cudaGetSymbolAddress((void**)&c5h,   g_c5h);
    cudaGetSymbolAddress((void**)&c5l,   g_c5l);
    cudaGetSymbolAddress((void**)&tb,    g_tb);
    cudaGetSymbolAddress((void**)&xxp,   g_xx);
    cudaGetSymbolAddress((void**)&idx,   g_idx);
    cudaGetSymbolAddress((void**)&pool,  g_pool);

    cudaFuncSetAttribute(mma_gemm, cudaFuncAttributeMaxDynamicSharedMemorySize, MMA_SMEM);
    cudaFuncSetAttribute(mma_gemm_pool_add, cudaFuncAttributeMaxDynamicSharedMemorySize,
                         MMA_SMEM_POOL);

    static cudaStream_t s2 = nullptr;
    static cudaEvent_t evf[4], evj[4], evc;
    if (s2 == nullptr) {
        cudaStreamCreateWithFlags(&s2, cudaStreamNonBlocking);
        for (int i = 0; i < 4; i++) {
            cudaEventCreateWithFlags(&evf[i], cudaEventDisableTiming);
            cudaEventCreateWithFlags(&evj[i], cudaEventDisableTiming);
        }
        cudaEventCreateWithFlags(&evc, cudaEventDisableTiming);
    }

    struct Layer {
        int inOff; int Cin; int Cout; int outOff;
        const float* W; const float* bias; const float* g; const float* bb;
    };
    Layer L[4] = {
        { -1,  3,   64,  0,   conv1_w, conv1_b, bn1_g, bn1_b },
        { 0,   64,  64,  64,  conv2_w, nullptr, bn2_g, bn2_b },
        { 64,  64,  128, 128, conv3_w, nullptr, bn3_g, bn3_b },
        { 128, 128, 256, 256, conv4_w, nullptr, bn4_g, bn4_b },
    };

    zero_pool<<<32, 256>>>(pool);

    for (int l = 0; l < 4; l++) {
        const Layer& a = L[l];
        const float* fin = (l == 0) ? x : (xc + a.inOff);
        int lda = (l == 0) ? 3 : 512;

        // fork: side stream computes [prep -> u|t GEMM]
        cudaEventRecord(evf[l], 0);
        cudaStreamWaitEvent(s2, evf[l], 0);

        if (l == 0)
            prep_c5<<<(1024 * 512 + 255) / 256, 256, 0, s2>>>(conv5_w, c5h, c5l);
        prep_w<<<(a.Cout * a.Cin + 255) / 256, 256, 0, s2>>>(
            a.W, a.Cin, a.Cout, a.bias, a.g, a.bb, utw, utwh, utwl, tb);
        if (l == 0) {
            gemm_f2<128, 64, 128><<<dim3(2, PTS / 128, 1), 128, 0, s2>>>(
                x, 3, 0, utw, 3, 0, ut, 128, 0, 3);
        } else {
            mma_gemm<<<dim3(2 * a.Cout / 128, PTS / 128, 1), 256, MMA_SMEM, s2>>>(
                xch + a.inOff, xcl + a.inOff, 512, 0,
                utwh, utwl, a.Cin, 0,
                ut, 2 * a.Cout, 0, a.Cin);
        }
        cudaEventRecord(evj[l], s2);

        // layer 4 fork also launches conv5 first half (K cols 0..255 —
        // features cols 0..255 are complete after layer-3 gathermax, which
        // precedes evf[3] on the main stream). Runs behind evj[3] so the
        // l4 gathermax is not delayed.
        if (l == 3) {
            mma_gemm<<<dim3(8, PTS / 128, 1), 256, MMA_SMEM, s2>>>(
                xch, xcl, 512, 0, c5h, c5l, 512, 0, e, 1024, 0, 256);
            cudaEventRecord(evc, s2);
        }

        // main stream: KNN chain
        gemm_sym<<<dim3(36, 1, B_), 256>>>(
            fin, lda, (long long)N_ * lda, inner, N_, (long long)N_ * N_, a.Cin);
        diag_xx<<<32, 256>>>(inner, xxp);
        topk_kernel<<<PTS / 8, 256>>>(inner, xxp, idx);

        // join, then gather
        cudaStreamWaitEvent(0, evj[l], 0);
        int cx = a.Cout / 4;
        int ppb = 1024 / a.Cout;
        if (ppb > 16) ppb = 16;
        gathermax<<<PTS / ppb, dim3(cx, ppb)>>>(ut, tb, idx, xc, xch, xcl,
                                                a.outOff, a.Cout);
    }

    // conv5 second half (K cols 256..511) + partial add + global max-pool
    cudaStreamWaitEvent(0, evc, 0);
    mma_gemm_pool_add<<<dim3(8, PTS / 128, 1), 256, MMA_SMEM_POOL>>>(
        xch + 256, xcl + 256, 512, c5h + 256, c5l + 256, 512,
        e, 1024, pool, 256);

    // fused MLP head
    mlp_head<<<B_, 512>>>(pool, lin1_w, bn6_g, bn6_b,
                          lin2_w, lin2_b, bn7_g, bn7_b,
                          lin3_w, lin3_b, (float*)d_out);
}

// round 12
// speedup vs baseline: 1.4721x; 1.4721x over previous
#include <cuda_runtime.h>
#include <cuda_bf16.h>
#include <cstdint>

// DGCNN forward. (Best-known R9 structure + fused MLP head.)
//   edge_conv:  out[b,n,o] = lrelu( max_k ( u[b,idx_k,o] + t[b,n,o] ) )
//   u = (s*W_a)@x ; t = (s*(W_b-W_a))@x + (s*bias + bn_b)
// KNN inner GEMMs: exact fp32 SIMT, symmetric (lower triangle + mirror).
// u|t GEMMs (l2-l4): bf16-split x3 mma.sync. conv5: same, fused with max-pool.
// Side stream carries only the thin [prep_w -> ut GEMM] chain.

#define B_   8
#define N_   1024
#define PTS  (B_ * N_)
#define KNN  20
#define NEG_INF __int_as_float(0xff800000)

__device__ static float          g_xc[PTS * 512];
__device__ static __nv_bfloat16  g_xch[PTS * 512];
__device__ static __nv_bfloat16  g_xcl[PTS * 512];
__device__ static float          g_inner[PTS * 1024];
__device__ static float          g_ut[PTS * 512];
__device__ static float          g_utw[512 * 128];
__device__ static __nv_bfloat16  g_utwh[512 * 128];
__device__ static __nv_bfloat16  g_utwl[512 * 128];
__device__ static __nv_bfloat16  g_c5h[1024 * 512];
__device__ static __nv_bfloat16  g_c5l[1024 * 512];
__device__ static float          g_tb[256];
__device__ static float          g_xx[PTS];
__device__ static int            g_idx[PTS * KNN];
__device__ static unsigned       g_pool[B_ * 1024];

__device__ __forceinline__ uint32_t smem_u32(const void* p) {
    uint32_t a;
    asm("{ .reg .u64 t; cvta.to.shared.u64 t, %1; cvt.u32.u64 %0, t; }"
        : "=r"(a) : "l"(p));
    return a;
}

__device__ __forceinline__ unsigned redux_max(unsigned v) {
    unsigned r;
    asm("redux.sync.max.u32 %0, %1, 0xffffffff;" : "=r"(r) : "r"(v));
    return r;
}

__device__ __forceinline__ unsigned fenc(float v) {
    unsigned u = __float_as_uint(v);
    return u ^ (((unsigned)((int)u >> 31)) | 0x80000000u);
}

#define LDSM_X4(r0, r1, r2, r3, addr) \
    asm volatile("ldmatrix.sync.aligned.m8n8.x4.shared.b16 {%0,%1,%2,%3}, [%4];" \
                 : "=r"(r0), "=r"(r1), "=r"(r2), "=r"(r3) : "r"(addr))

#define MMA_BF16(c, a, b0, b1) \
    asm volatile( \
        "mma.sync.aligned.m16n8k16.row.col.f32.bf16.bf16.f32 " \
        "{%0,%1,%2,%3}, {%4,%5,%6,%7}, {%8,%9}, {%0,%1,%2,%3};" \
        : "+f"((c)[0]), "+f"((c)[1]), "+f"((c)[2]), "+f"((c)[3]) \
        : "r"((a)[0]), "r"((a)[1]), "r"((a)[2]), "r"((a)[3]), \
          "r"(b0), "r"(b1))

// ---------------------------------------------------------------------------
// bf16-split mma.sync GEMM mainloop (shared)
// ---------------------------------------------------------------------------
#define SKA       40
#define TILE_B    (128 * SKA * 2)
#define STAGE_B   (4 * TILE_B)
#define MMA_SMEM  (2 * STAGE_B)
#define MMA_SMEM_POOL (2 * STAGE_B + 512)

struct MmaCtx {
    float acc[4][4][4];
    int m_warp, n_warp, lane;
};

__device__ __forceinline__ void mma_mainloop(
    char* smem, uint32_t sb0, MmaCtx& cx,
    const __nv_bfloat16* Ah, const __nv_bfloat16* Al, int lda, int m0,
    const __nv_bfloat16* Bh, const __nv_bfloat16* Bl, int ldb, int n0, int K)
{
    const int tid  = threadIdx.x;
    const int wid  = tid >> 5;
    const int lane = tid & 31;
    cx.lane = lane;
    cx.m_warp = (wid & 1) * 64;
    cx.n_warp = (wid >> 1) * 32;

    #pragma unroll
    for (int i = 0; i < 4; i++)
        #pragma unroll
        for (int j = 0; j < 4; j++)
            #pragma unroll
            for (int q = 0; q < 4; q++) cx.acc[i][j][q] = 0.f;

    uint4 stg[8];
    auto ldG = [&](int kc) {
        #pragma unroll
        for (int i = 0; i < 8; i++) {
            int u = tid + i * 256;
            int tile = u >> 9;
            int r = (u >> 2) & 127;
            int q = u & 3;
            const __nv_bfloat16* src;
            int ld_, r0;
            if (tile == 0)      { src = Ah; ld_ = lda; r0 = m0; }
            else if (tile == 1) { src = Al; ld_ = lda; r0 = m0; }
            else if (tile == 2) { src = Bh; ld_ = ldb; r0 = n0; }
            else                { src = Bl; ld_ = ldb; r0 = n0; }
            stg[i] = *reinterpret_cast<const uint4*>(
                src + (size_t)(r0 + r) * ld_ + kc + q * 8);
        }
    };
    auto stS = [&](int stage) {
        char* base = smem + stage * STAGE_B;
        #pragma unroll
        for (int i = 0; i < 8; i++) {
            int u = tid + i * 256;
            int tile = u >> 9;
            int r = (u >> 2) & 127;
            int q = u & 3;
            *reinterpret_cast<uint4*>(base + tile * TILE_B + r * (SKA * 2) + q * 16) = stg[i];
        }
    };

    const int nc = K >> 5;
    ldG(0); stS(0);
    __syncthreads();

    for (int c = 0; c < nc; c++) {
        int buf = c & 1;
        if (c + 1 < nc) ldG((c + 1) * 32);

        const uint32_t sb = sb0 + buf * STAGE_B;
        #pragma unroll
        for (int ks = 0; ks < 32; ks += 16) {
            uint32_t ah[4][4], al[4][4], bh[2][4], bl[2][4];
            const uint32_t lrow = (lane & 15);
            const uint32_t lcol = (lane >> 4) * 8;
            #pragma unroll
            for (int mt = 0; mt < 4; mt++) {
                uint32_t off = ((cx.m_warp + mt * 16 + lrow) * SKA + ks + lcol) * 2;
                LDSM_X4(ah[mt][0], ah[mt][1], ah[mt][2], ah[mt][3], sb + off);
                LDSM_X4(al[mt][0], al[mt][1], al[mt][2], al[mt][3], sb + TILE_B + off);
            }
            #pragma unroll
            for (int np = 0; np < 2; np++) {
                uint32_t off = ((cx.n_warp + np * 16 + lrow) * SKA + ks + lcol) * 2;
                LDSM_X4(bh[np][0], bh[np][1], bh[np][2], bh[np][3], sb + 2 * TILE_B + off);
                LDSM_X4(bl[np][0], bl[np][1], bl[np][2], bl[np][3], sb + 3 * TILE_B + off);
            }
            #pragma unroll
            for (int mt = 0; mt < 4; mt++)
                #pragma unroll
                for (int nt = 0; nt < 4; nt++) {
                    int np = nt >> 1, half = nt & 1;
                    MMA_BF16(cx.acc[mt][nt], ah[mt], bh[np][half], bh[np][2 + half]);
                    MMA_BF16(cx.acc[mt][nt], ah[mt], bl[np][half], bl[np][2 + half]);
                    MMA_BF16(cx.acc[mt][nt], al[mt], bh[np][half], bh[np][2 + half]);
                }
        }

        if (c + 1 < nc) stS(buf ^ 1);
        __syncthreads();
    }
}

__global__ void __launch_bounds__(256)
mma_gemm(const __nv_bfloat16* __restrict__ Ah, const __nv_bfloat16* __restrict__ Al,
         int lda, long long sA,
         const __nv_bfloat16* __restrict__ Bh, const __nv_bfloat16* __restrict__ Bl,
         int ldb, long long sB,
         float* __restrict__ C, int ldc, long long sC, int K)
{
    extern __shared__ char smem[];
    const uint32_t sb0 = smem_u32(smem);
    const int bz = blockIdx.z;
    Ah += bz * sA; Al += bz * sA; Bh += bz * sB; Bl += bz * sB; C += bz * sC;
    const int m0 = blockIdx.y * 128;
    const int n0 = blockIdx.x * 128;

    MmaCtx cx;
    mma_mainloop(smem, sb0, cx, Ah, Al, lda, m0, Bh, Bl, ldb, n0, K);

    #pragma unroll
    for (int mt = 0; mt < 4; mt++)
        #pragma unroll
        for (int nt = 0; nt < 4; nt++) {
            int rm = m0 + cx.m_warp + mt * 16 + (cx.lane >> 2);
            int cn = n0 + cx.n_warp + nt * 8 + (cx.lane & 3) * 2;
            *reinterpret_cast<float2*>(&C[(size_t)rm * ldc + cn]) =
                make_float2(cx.acc[mt][nt][0], cx.acc[mt][nt][1]);
            *reinterpret_cast<float2*>(&C[(size_t)(rm + 8) * ldc + cn]) =
                make_float2(cx.acc[mt][nt][2], cx.acc[mt][nt][3]);
        }
}

// conv5 variant: no C store; row-max reduce; atomicMax into pool.
__global__ void __launch_bounds__(256)
mma_gemm_pool(const __nv_bfloat16* __restrict__ Ah, const __nv_bfloat16* __restrict__ Al,
              int lda,
              const __nv_bfloat16* __restrict__ Bh, const __nv_bfloat16* __restrict__ Bl,
              int ldb,
              unsigned* __restrict__ pool, int K)
{
    extern __shared__ char smem[];
    const uint32_t sb0 = smem_u32(smem);
    unsigned* spool = reinterpret_cast<unsigned*>(smem + 2 * STAGE_B);
    const int tid = threadIdx.x;
    if (tid < 128) spool[tid] = 0u;

    const int m0 = blockIdx.y * 128;
    const int n0 = blockIdx.x * 128;
    const int b  = m0 >> 10;

    MmaCtx cx;
    mma_mainloop(smem, sb0, cx, Ah, Al, lda, m0, Bh, Bl, ldb, n0, K);

    #pragma unroll
    for (int nt = 0; nt < 4; nt++)
        #pragma unroll
        for (int j = 0; j < 2; j++) {
            float v = NEG_INF;
            #pragma unroll
            for (int mt = 0; mt < 4; mt++)
                v = fmaxf(v, fmaxf(cx.acc[mt][nt][j], cx.acc[mt][nt][2 + j]));
            v = fmaxf(v, __shfl_xor_sync(0xffffffffu, v, 4));
            v = fmaxf(v, __shfl_xor_sync(0xffffffffu, v, 8));
            v = fmaxf(v, __shfl_xor_sync(0xffffffffu, v, 16));
            if ((cx.lane >> 2) == 0) {
                unsigned uu = __float_as_uint(v);
                uu = (uu >> 31) ? ~uu : (uu | 0x80000000u);
                atomicMax(&spool[cx.n_warp + nt * 8 + (cx.lane & 3) * 2 + j], uu);
            }
        }
    __syncthreads();
    if (tid < 128) atomicMax(&pool[b * 1024 + n0 + tid], spool[tid]);
}

// ---------------------------------------------------------------------------
// fp32 SIMT GEMM machinery (exact path)
// ---------------------------------------------------------------------------
#define FMA_F32X2(d, a, b, c) \
    asm("fma.rn.f32x2 %0, %1, %2, %3;" : "=l"(d) : "l"(a), "l"(b), "l"(c))
__device__ __forceinline__ float f2lo(unsigned long long v) {
    return __uint_as_float((unsigned)(v & 0xffffffffull));
}
__device__ __forceinline__ float f2hi(unsigned long long v) {
    return __uint_as_float((unsigned)(v >> 32));
}

template<int BM, int BN, int TH>
__global__ void __launch_bounds__(TH, 2)
gemm_f2(const float* __restrict__ A, int lda, long long sA,
        const float* __restrict__ B, int ldb, long long sB,
        float* __restrict__ C, int ldc, long long sC, int K)
{
    constexpr int BK = 8;
    constexpr int LA = 2 * BM + 4;
    constexpr int LB = BN + 4;
    constexpr int NX = BN / 8;
    constexpr int NY = BM / 8;
    static_assert(NX * NY == TH, "threads");
    constexpr int CA = (BM * 2) / TH;
    constexpr int CB = (BN * 2) / TH;

    __shared__ float As2[2][BK][LA];
    __shared__ float Bs[2][BK][LB];

    const int bz = blockIdx.z;
    A += bz * sA; B += bz * sB; C += bz * sC;
    const int m0 = blockIdx.y * BM;
    const int n0 = blockIdx.x * BN;
    const int tid = threadIdx.x;
    const int tx = tid % NX;
    const int ty = tid / NX;
    const bool a4 = ((lda & 3) == 0);
    const bool b4 = ((ldb & 3) == 0);

    unsigned long long acc[8][4];
    #pragma unroll
    for (int i = 0; i < 8; i++)
        #pragma unroll
        for (int j = 0; j < 4; j++) acc[i][j] = 0ull;

    float4 stA[CA], stB[CB];
    auto ldGA = [&](int k0) {
        #pragma unroll
        for (int i = 0; i < CA; i++) {
            int f4 = tid + i * TH;
            int row = f4 >> 1, kq = (f4 & 1) << 2;
            int k = k0 + kq;
            const float* p = A + (size_t)(m0 + row) * lda;
            float4 v;
            if (a4 && (k + 3) < K) v = *reinterpret_cast<const float4*>(p + k);
            else {
                v.x = (k     < K) ? p[k]     : 0.f;
                v.y = (k + 1 < K) ? p[k + 1] : 0.f;
                v.z = (k + 2 < K) ? p[k + 2] : 0.f;
                v.w = (k + 3 < K) ? p[k + 3] : 0.f;
            }
            stA[i] = v;
        }
    };
    auto ldGB = [&](int k0) {
        #pragma unroll
        for (int i = 0; i < CB; i++) {
            int f4 = tid + i * TH;
            int row = f4 >> 1, kq = (f4 & 1) << 2;
            int k = k0 + kq;
            const float* p = B + (size_t)(n0 + row) * ldb;
            float4 v;
            if (b4 && (k + 3) < K) v = *reinterpret_cast<const float4*>(p + k);
            else {
                v.x = (k     < K) ? p[k]     : 0.f;
                v.y = (k + 1 < K) ? p[k + 1] : 0.f;
                v.z = (k + 2 < K) ? p[k + 2] : 0.f;
                v.w = (k + 3 < K) ? p[k + 3] : 0.f;
            }
            stB[i] = v;
        }
    };
    auto stS = [&](int buf) {
        #pragma unroll
        for (int i = 0; i < CA; i++) {
            int f4 = tid + i * TH;
            int row = f4 >> 1, kq = (f4 & 1) << 2;
            float vv[4] = {stA[i].x, stA[i].y, stA[i].z, stA[i].w};
            #pragma unroll
            for (int j = 0; j < 4; j++)
                *reinterpret_cast<float2*>(&As2[buf][kq + j][2 * row]) =
                    make_float2(vv[j], vv[j]);
        }
        #pragma unroll
        for (int i = 0; i < CB; i++) {
            int f4 = tid + i * TH;
            int row = f4 >> 1, kq = (f4 & 1) << 2;
            Bs[buf][kq + 0][row] = stB[i].x;
            Bs[buf][kq + 1][row] = stB[i].y;
            Bs[buf][kq + 2][row] = stB[i].z;
            Bs[buf][kq + 3][row] = stB[i].w;
        }
    };

    const int nt = (K + BK - 1) / BK;
    ldGA(0); ldGB(0); stS(0);
    __syncthreads();

    for (int t = 0; t < nt; t++) {
        int buf = t & 1;
        if (t + 1 < nt) { ldGA((t + 1) * BK); ldGB((t + 1) * BK); }
        #pragma unroll
        for (int k = 0; k < BK; k++) {
            ulonglong2 a01 = *reinterpret_cast<const ulonglong2*>(&As2[buf][k][2 * (ty * 4)]);
            ulonglong2 a23 = *reinterpret_cast<const ulonglong2*>(&As2[buf][k][2 * (ty * 4) + 4]);
            ulonglong2 a45 = *reinterpret_cast<const ulonglong2*>(&As2[buf][k][2 * (BM / 2 + ty * 4)]);
            ulonglong2 a67 = *reinterpret_cast<const ulonglong2*>(&As2[buf][k][2 * (BM / 2 + ty * 4) + 4]);
            ulonglong2 b01 = *reinterpret_cast<const ulonglong2*>(&Bs[buf][k][tx * 4]);
            ulonglong2 b23 = *reinterpret_cast<const ulonglong2*>(&Bs[buf][k][BN / 2 + tx * 4]);
            unsigned long long av[8] = {a01.x, a01.y, a23.x, a23.y,
                                        a45.x, a45.y, a67.x, a67.y};
            unsigned long long bv[4] = {b01.x, b01.y, b23.x, b23.y};
            #pragma unroll
            for (int i = 0; i < 8; i++)
                #pragma unroll
                for (int j = 0; j < 4; j++)
                    FMA_F32X2(acc[i][j], av[i], bv[j], acc[i][j]);
        }
        if (t + 1 < nt) stS(buf ^ 1);
        __syncthreads();
    }

    #pragma unroll
    for (int i = 0; i < 8; i++) {
        int m = m0 + ((i < 4) ? (ty * 4 + i) : (BM / 2 + ty * 4 + i - 4));
        float4 o0, o1;
        o0.x = f2lo(acc[i][0]); o0.y = f2hi(acc[i][0]);
        o0.z = f2lo(acc[i][1]); o0.w = f2hi(acc[i][1]);
        o1.x = f2lo(acc[i][2]); o1.y = f2hi(acc[i][2]);
        o1.z = f2lo(acc[i][3]); o1.w = f2hi(acc[i][3]);
        *reinterpret_cast<float4*>(&C[(size_t)m * ldc + n0 + tx * 4]) = o0;
        *reinterpret_cast<float4*>(&C[(size_t)m * ldc + n0 + BN / 2 + tx * 4]) = o1;
    }
}

// ---------------------------------------------------------------------------
// Symmetric fp32 GEMM: C = X.X^T per batch (lower triangle + mirror store).
// ---------------------------------------------------------------------------
__global__ void __launch_bounds__(256, 2)
gemm_sym(const float* __restrict__ X, int lda, long long sX,
         float* __restrict__ C, int ldc, long long sC, int K)
{
    constexpr int BM = 128, BN = 128, BK = 8;
    constexpr int LA = 2 * BM + 4;
    constexpr int LB = BN + 4;
    constexpr int NX = BN / 8;

    __shared__ float As2[2][BK][LA];
    __shared__ float Bs[2][BK][LB];

    int t = blockIdx.x;
    int i_ = (int)((sqrtf(8.f * t + 1.f) - 1.f) * 0.5f);
    while ((i_ + 1) * (i_ + 2) / 2 <= t) i_++;
    while (i_ * (i_ + 1) / 2 > t) i_--;
    int j_ = t - i_ * (i_ + 1) / 2;

    const int bz = blockIdx.z;
    const float* A = X + bz * sX;
    float* Cb = C + bz * sC;
    const int m0 = i_ * BM;
    const int n0 = j_ * BN;
    const int tid = threadIdx.x;
    const int tx = tid % NX;
    const int ty = tid / NX;
    const bool a4 = ((lda & 3) == 0);

    unsigned long long acc[8][4];
    #pragma unroll
    for (int i = 0; i < 8; i++)
        #pragma unroll
        for (int j = 0; j < 4; j++) acc[i][j] = 0ull;

    float4 stA[1], stB[1];
    auto ldGA = [&](int k0) {
        int row = tid >> 1, kq = (tid & 1) << 2;
        int k = k0 + kq;
        const float* p = A + (size_t)(m0 + row) * lda;
        float4 v;
        if (a4 && (k + 3) < K) v = *reinterpret_cast<const float4*>(p + k);
        else {
            v.x = (k     < K) ? p[k]     : 0.f;
            v.y = (k + 1 < K) ? p[k + 1] : 0.f;
            v.z = (k + 2 < K) ? p[k + 2] : 0.f;
            v.w = (k + 3 < K) ? p[k + 3] : 0.f;
        }
        stA[0] = v;
    };
    auto ldGB = [&](int k0) {
        int row = tid >> 1, kq = (tid & 1) << 2;
        int k = k0 + kq;
        const float* p = A + (size_t)(n0 + row) * lda;
        float4 v;
        if (a4 && (k + 3) < K) v = *reinterpret_cast<const float4*>(p + k);
        else {
            v.x = (k     < K) ? p[k]     : 0.f;
            v.y = (k + 1 < K) ? p[k + 1] : 0.f;
            v.z = (k + 2 < K) ? p[k + 2] : 0.f;
            v.w = (k + 3 < K) ? p[k + 3] : 0.f;
        }
        stB[0] = v;
    };
    auto stS = [&](int buf) {
        int row = tid >> 1, kq = (tid & 1) << 2;
        float vv[4] = {stA[0].x, stA[0].y, stA[0].z, stA[0].w};
        #pragma unroll
        for (int j = 0; j < 4; j++)
            *reinterpret_cast<float2*>(&As2[buf][kq + j][2 * row]) =
                make_float2(vv[j], vv[j]);
        Bs[buf][kq + 0][row] = stB[0].x;
        Bs[buf][kq + 1][row] = stB[0].y;
        Bs[buf][kq + 2][row] = stB[0].z;
        Bs[buf][kq + 3][row] = stB[0].w;
    };

    const int nt = (K + BK - 1) / BK;
    ldGA(0); ldGB(0); stS(0);
    __syncthreads();

    for (int tt = 0; tt < nt; tt++) {
        int buf = tt & 1;
        if (tt + 1 < nt) { ldGA((tt + 1) * BK); ldGB((tt + 1) * BK); }
        #pragma unroll
        for (int k = 0; k < BK; k++) {
            ulonglong2 a01 = *reinterpret_cast<const ulonglong2*>(&As2[buf][k][2 * (ty * 4)]);
            ulonglong2 a23 = *reinterpret_cast<const ulonglong2*>(&As2[buf][k][2 * (ty * 4) + 4]);
            ulonglong2 a45 = *reinterpret_cast<const ulonglong2*>(&As2[buf][k][2 * (BM / 2 + ty * 4)]);
            ulonglong2 a67 = *reinterpret_cast<const ulonglong2*>(&As2[buf][k][2 * (BM / 2 + ty * 4) + 4]);
            ulonglong2 b01 = *reinterpret_cast<const ulonglong2*>(&Bs[buf][k][tx * 4]);
            ulonglong2 b23 = *reinterpret_cast<const ulonglong2*>(&Bs[buf][k][BN / 2 + tx * 4]);
            unsigned long long av[8] = {a01.x, a01.y, a23.x, a23.y,
                                        a45.x, a45.y, a67.x, a67.y};
            unsigned long long bv[4] = {b01.x, b01.y, b23.x, b23.y};
            #pragma unroll
            for (int i = 0; i < 8; i++)
                #pragma unroll
                for (int j = 0; j < 4; j++)
                    FMA_F32X2(acc[i][j], av[i], bv[j], acc[i][j]);
        }
        if (tt + 1 < nt) stS(buf ^ 1);
        __syncthreads();
    }

    float f[8][8];
    int mrow[8], ncol[8];
    #pragma unroll
    for (int i = 0; i < 8; i++) {
        mrow[i] = m0 + ((i < 4) ? (ty * 4 + i) : (64 + ty * 4 + i - 4));
        ncol[i] = n0 + ((i < 4) ? (tx * 4 + i) : (64 + tx * 4 + i - 4));
        f[i][0] = f2lo(acc[i][0]); f[i][1] = f2hi(acc[i][0]);
        f[i][2] = f2lo(acc[i][1]); f[i][3] = f2hi(acc[i][1]);
        f[i][4] = f2lo(acc[i][2]); f[i][5] = f2hi(acc[i][2]);
        f[i][6] = f2lo(acc[i][3]); f[i][7] = f2hi(acc[i][3]);
    }

    #pragma unroll
    for (int i = 0; i < 8; i++) {
        *reinterpret_cast<float4*>(&Cb[(size_t)mrow[i] * ldc + ncol[0]]) =
            make_float4(f[i][0], f[i][1], f[i][2], f[i][3]);
        *reinterpret_cast<float4*>(&Cb[(size_t)mrow[i] * ldc + ncol[4]]) =
            make_float4(f[i][4], f[i][5], f[i][6], f[i][7]);
    }
    if (i_ != j_) {
        #pragma unroll
        for (int q = 0; q < 8; q++) {
            *reinterpret_cast<float4*>(&Cb[(size_t)ncol[q] * ldc + mrow[0]]) =
                make_float4(f[0][q], f[1][q], f[2][q], f[3][q]);
            *reinterpret_cast<float4*>(&Cb[(size_t)ncol[q] * ldc + mrow[4]]) =
                make_float4(f[4][q], f[5][q], f[6][q], f[7][q]);
        }
    }
}

// ---------------------------------------------------------------------------
__global__ void diag_xx(const float* __restrict__ inner, float* __restrict__ xx)
{
    int p = blockIdx.x * 256 + threadIdx.x;
    if (p < PTS) xx[p] = inner[(size_t)p * N_ + (p & (N_ - 1))];
}

// ---------------------------------------------------------------------------
// top-20: warp per row, float4 scan, u32 key top-2 cache + index regs,
// pops via redux.sync.max.u32 pair.
// ---------------------------------------------------------------------------
__device__ __forceinline__ void tk_upd(unsigned& k1, unsigned& m1,
                                       unsigned& k2, unsigned& m2,
                                       unsigned e, unsigned m) {
    if (e > k1)      { k2 = k1; m2 = m1; k1 = e; m1 = m; }
    else if (e > k2) { k2 = e; m2 = m; }
}

__global__ void __launch_bounds__(256)
topk_kernel(const float* __restrict__ inner, const float* __restrict__ xx,
            int* __restrict__ idx_out)
{
    __shared__ uint4 s4[8][N_ / 4];
    int wid  = threadIdx.x >> 5;
    int lane = threadIdx.x & 31;
    int row  = blockIdx.x * 8 + wid;
    int b    = row >> 10;
    uint4* sw4 = s4[wid];
    unsigned* sw = reinterpret_cast<unsigned*>(sw4);
    const float4* r4 = reinterpret_cast<const float4*>(inner + (size_t)row * N_);
    const float4* x4 = reinterpret_cast<const float4*>(xx + (b << 10));

    unsigned k1 = 0, m1 = 0, k2 = 0, m2 = 0;
    #pragma unroll
    for (int i = 0; i < 8; i++) {
        int q = i * 32 + lane;
        float4 rv = r4[q];
        float4 xv = x4[q];
        unsigned mb = (unsigned)q * 4;
        unsigned e0 = fenc(fmaf(2.f, rv.x, -xv.x));
        unsigned e1 = fenc(fmaf(2.f, rv.y, -xv.y));
        unsigned e2 = fenc(fmaf(2.f, rv.z, -xv.z));
        unsigned e3 = fenc(fmaf(2.f, rv.w, -xv.w));
        sw4[q] = make_uint4(e0, e1, e2, e3);
        tk_upd(k1, m1, k2, m2, e0, mb);
        tk_upd(k1, m1, k2, m2, e1, mb + 1);
        tk_upd(k1, m1, k2, m2, e2, mb + 2);
        tk_upd(k1, m1, k2, m2, e3, mb + 3);
    }
    __syncwarp();

    for (int it = 0; it < KNN; it++) {
        unsigned wkey = redux_max(k1);
        unsigned cand = (k1 == wkey) ? (1023u - m1) : 0u;
        unsigned widx = redux_max(cand);
        unsigned m = 1023u - widx;
        if (lane == 0) idx_out[row * KNN + it] = (int)m;
        if (k1 == wkey && (1023u - m1) == widx) {
            sw[m] = 0;
            k1 = k2; m1 = m2; k2 = 0; m2 = 0;
            if (k1 == 0) {
                #pragma unroll
                for (int i = 0; i < 8; i++) {
                    int q = i * 32 + lane;
                    uint4 v = sw4[q];
                    unsigned mb = (unsigned)q * 4;
                    tk_upd(k1, m1, k2, m2, v.x, mb);
                    tk_upd(k1, m1, k2, m2, v.y, mb + 1);
                    tk_upd(k1, m1, k2, m2, v.z, mb + 2);
                    tk_upd(k1, m1, k2, m2, v.w, mb + 3);
                }
            }
        }
        __syncwarp();
    }
}

// ---------------------------------------------------------------------------
__device__ __forceinline__ void split_store(float v, __nv_bfloat16* h, __nv_bfloat16* l,
                                            size_t i)
{
    __nv_bfloat16 hb = __float2bfloat16(v);
    h[i] = hb;
    l[i] = __float2bfloat16(v - __bfloat162float(hb));
}

__global__ void prep_w(const float* __restrict__ W, int C, int O,
                       const float* __restrict__ bias,
                       const float* __restrict__ bng, const float* __restrict__ bnb,
                       float* __restrict__ utw,
                       __nv_bfloat16* __restrict__ utwh, __nv_bfloat16* __restrict__ utwl,
                       float* __restrict__ tb)
{
    const float inv = 1.0f / sqrtf(1.00001f);
    int i = blockIdx.x * 256 + threadIdx.x;
    if (i < O * C) {
        int o = i / C, c = i - o * C;
        float s = bng[o] * inv;
        float wa = W[o * 2 * C + c];
        float wb = W[o * 2 * C + C + c];
        float vu = s * wa;
        float vt = s * (wb - wa);
        utw[(size_t)o * C + c] = vu;
        utw[(size_t)(O + o) * C + c] = vt;
        split_store(vu, utwh, utwl, (size_t)o * C + c);
        split_store(vt, utwh, utwl, (size_t)(O + o) * C + c);
    }
    if (i < O) {
        float s = bng[i] * inv;
        tb[i] = s * (bias ? bias[i] : 0.f) + bnb[i];
    }
}

__global__ void prep_c5(const float* __restrict__ W,
                        __nv_bfloat16* __restrict__ h, __nv_bfloat16* __restrict__ l)
{
    int i = blockIdx.x * 256 + threadIdx.x;
    if (i < 1024 * 512) split_store(W[i], h, l, i);
}

// ---------------------------------------------------------------------------
__global__ void gathermax(const float* __restrict__ ut, const float* __restrict__ tb,
                          const int* __restrict__ idx,
                          float* __restrict__ xc,
                          __nv_bfloat16* __restrict__ xch, __nv_bfloat16* __restrict__ xcl,
                          int colOff, int CO)
{
    __shared__ int sidx[16][KNN];
    int ty = threadIdx.y, tx = threadIdx.x;
    int p = blockIdx.x * blockDim.y + ty;
    int b = p >> 10;
    for (int k = tx; k < KNN; k += blockDim.x) sidx[ty][k] = idx[p * KNN + k];
    __syncthreads();

    int st = 2 * CO;
    float4 tv = *reinterpret_cast<const float4*>(ut + (size_t)p * st + CO + tx * 4);
    float4 bv = *reinterpret_cast<const float4*>(tb + tx * 4);
    tv.x += bv.x; tv.y += bv.y; tv.z += bv.z; tv.w += bv.w;

    float4 mx = make_float4(NEG_INF, NEG_INF, NEG_INF, NEG_INF);
    #pragma unroll 4
    for (int k = 0; k < KNN; k++) {
        int j = sidx[ty][k];
        float4 v = *reinterpret_cast<const float4*>(
            ut + (size_t)((b << 10) + j) * st + tx * 4);
        mx.x = fmaxf(mx.x, v.x + tv.x);
        mx.y = fmaxf(mx.y, v.y + tv.y);
        mx.z = fmaxf(mx.z, v.z + tv.z);
        mx.w = fmaxf(mx.w, v.w + tv.w);
    }
    mx.x = (mx.x >= 0.f) ? mx.x : 0.01f * mx.x;
    mx.y = (mx.y >= 0.f) ? mx.y : 0.01f * mx.y;
    mx.z = (mx.z >= 0.f) ? mx.z : 0.01f * mx.z;
    mx.w = (mx.w >= 0.f) ? mx.w : 0.01f * mx.w;

    size_t o = (size_t)p * 512 + colOff + tx * 4;
    *reinterpret_cast<float4*>(xc + o) = mx;

    float vals[4] = {mx.x, mx.y, mx.z, mx.w};
    __nv_bfloat16 hb[4], lb[4];
    #pragma unroll
    for (int i = 0; i < 4; i++) {
        hb[i] = __float2bfloat16(vals[i]);
        lb[i] = __float2bfloat16(vals[i] - __bfloat162float(hb[i]));
    }
    *reinterpret_cast<uint2*>(xch + o) = *reinterpret_cast<uint2*>(hb);
    *reinterpret_cast<uint2*>(xcl + o) = *reinterpret_cast<uint2*>(lb);
}

// ---------------------------------------------------------------------------
__global__ void zero_pool(unsigned* pool)
{
    int i = blockIdx.x * 256 + threadIdx.x;
    if (i < B_ * 1024) pool[i] = 0u;
}

__device__ __forceinline__ float dec_pool(unsigned u)
{
    return (u & 0x80000000u) ? __uint_as_float(u & 0x7fffffffu) : __uint_as_float(~u);
}

// ---------------------------------------------------------------------------
// fused MLP head: block per batch, warp-per-output (same reduction order as
// the separate kernels -> bit-identical).
// ---------------------------------------------------------------------------
__global__ void __launch_bounds__(512)
mlp_head(const unsigned* __restrict__ pool,
         const float* __restrict__ w1, const float* __restrict__ g6,
         const float* __restrict__ b6,
         const float* __restrict__ w2, const float* __restrict__ wb2,
         const float* __restrict__ g7, const float* __restrict__ b7,
         const float* __restrict__ w3, const float* __restrict__ wb3,
         float* __restrict__ out)
{
    __shared__ float sp[1024];
    __shared__ float sy1[512];
    __shared__ float sy2[256];
    const int b = blockIdx.x;
    const int tid = threadIdx.x;
    const int wid = tid >> 5, lane = tid & 31;
    const float inv = 1.0f / sqrtf(1.00001f);

    for (int i = tid; i < 1024; i += 512) sp[i] = dec_pool(pool[b * 1024 + i]);
    __syncthreads();

    for (int j = wid; j < 512; j += 16) {
        const float* wr = w1 + (size_t)j * 1024;
        float s = 0.f;
        for (int c = lane; c < 1024; c += 32) s += sp[c] * wr[c];
        #pragma unroll
        for (int off = 16; off; off >>= 1) s += __shfl_xor_sync(0xffffffffu, s, off);
        if (lane == 0) {
            float v = s * (g6[j] * inv) + b6[j];
            sy1[j] = (v >= 0.f) ? v : 0.01f * v;
        }
    }
    __syncthreads();

    for (int j = wid; j < 256; j += 16) {
        const float* wr = w2 + (size_t)j * 512;
        float s = 0.f;
        for (int c = lane; c < 512; c += 32) s += sy1[c] * wr[c];
        #pragma unroll
        for (int off = 16; off; off >>= 1) s += __shfl_xor_sync(0xffffffffu, s, off);
        if (lane == 0) {
            float v = (s + wb2[j]) * (g7[j] * inv) + b7[j];
            sy2[j] = (v >= 0.f) ? v : 0.01f * v;
        }
    }
    __syncthreads();

    for (int j = wid; j < 40; j += 16) {
        const float* wr = w3 + (size_t)j * 256;
        float s = 0.f;
        for (int c = lane; c < 256; c += 32) s += sy2[c] * wr[c];
        #pragma unroll
        for (int off = 16; off; off >>= 1) s += __shfl_xor_sync(0xffffffffu, s, off);
        if (lane == 0) out[b * 40 + j] = s + wb3[j];
    }
}

// ---------------------------------------------------------------------------
extern "C" void kernel_launch(void* const* d_in, const int* in_sizes, int n_in,
                              void* d_out, int out_size)
{
    const float* x        = (const float*)d_in[0];
    const float* conv1_w  = (const float*)d_in[1];
    const float* conv1_b  = (const float*)d_in[2];
    const float* bn1_g    = (const float*)d_in[3];
    const float* bn1_b    = (const float*)d_in[4];
    const float* conv2_w  = (const float*)d_in[5];
    const float* bn2_g    = (const float*)d_in[6];
    const float* bn2_b    = (const float*)d_in[7];
    const float* conv3_w  = (const float*)d_in[8];
    const float* bn3_g    = (const float*)d_in[9];
    const float* bn3_b    = (const float*)d_in[10];
    const float* conv4_w  = (const float*)d_in[11];
    const float* bn4_g    = (const float*)d_in[12];
    const float* bn4_b    = (const float*)d_in[13];
    const float* conv5_w  = (const float*)d_in[14];
    const float* lin1_w   = (const float*)d_in[15];
    const float* bn6_g    = (const float*)d_in[16];
    const float* bn6_b    = (const float*)d_in[17];
    const float* lin2_w   = (const float*)d_in[18];
    const float* lin2_b   = (const float*)d_in[19];
    const float* bn7_g    = (const float*)d_in[20];
    const float* bn7_b    = (const float*)d_in[21];
    const float* lin3_w   = (const float*)d_in[22];
    const float* lin3_b   = (const float*)d_in[23];

    float *xc, *inner, *ut, *utw, *tb, *xxp;
    __nv_bfloat16 *xch, *xcl, *utwh, *utwl, *c5h, *c5l;
    int* idx; unsigned* pool;
    cudaGetSymbolAddress((void**)&xc,    g_xc);
    cudaGetSymbolAddress((void**)&inner, g_inner);
    cudaGetSymbolAddress((void**)&xch,   g_xch);
    cudaGetSymbolAddress((void**)&xcl,   g_xcl);
    cudaGetSymbolAddress((void**)&ut,    g_ut);
    cudaGetSymbolAddress((void**)&utw,   g_utw);
    cudaGetSymbolAddress((void**)&utwh,  g_utwh);
    cudaGetSymbolAddress((void**)&utwl,  g_utwl);
    cudaGetSymbolAddress((void**)&c5h,   g_c5h);
    cudaGetSymbolAddress((void**)&c5l,   g_c5l);
    cudaGetSymbolAddress((void**)&tb,    g_tb);
    cudaGetSymbolAddress((void**)&xxp,   g_xx);
    cudaGetSymbolAddress((void**)&idx,   g_idx);
    cudaGetSymbolAddress((void**)&pool,  g_pool);

    cudaFuncSetAttribute(mma_gemm, cudaFuncAttributeMaxDynamicSharedMemorySize, MMA_SMEM);
    cudaFuncSetAttribute(mma_gemm_pool, cudaFuncAttributeMaxDynamicSharedMemorySize,
                         MMA_SMEM_POOL);

    static cudaStream_t s2 = nullptr;
    static cudaEvent_t evf[4], evj[4];
    if (s2 == nullptr) {
        cudaStreamCreateWithFlags(&s2, cudaStreamNonBlocking);
        for (int i = 0; i < 4; i++) {
            cudaEventCreateWithFlags(&evf[i], cudaEventDisableTiming);
            cudaEventCreateWithFlags(&evj[i], cudaEventDisableTiming);
        }
    }

    struct Layer {
        int inOff; int Cin; int Cout; int outOff;
        const float* W; const float* bias; const float* g; const float* bb;
    };
    Layer L[4] = {
        { -1,  3,   64,  0,   conv1_w, conv1_b, bn1_g, bn1_b },
        { 0,   64,  64,  64,  conv2_w, nullptr, bn2_g, bn2_b },
        { 64,  64,  128, 128, conv3_w, nullptr, bn3_g, bn3_b },
        { 128, 128, 256, 256, conv4_w, nullptr, bn4_g, bn4_b },
    };

    zero_pool<<<32, 256>>>(pool);

    for (int l = 0; l < 4; l++) {
        const Layer& a = L[l];
        const float* fin = (l == 0) ? x : (xc + a.inOff);
        int lda = (l == 0) ? 3 : 512;

        // fork: side stream computes the thin [prep -> u|t GEMM] chain
        cudaEventRecord(evf[l], 0);
        cudaStreamWaitEvent(s2, evf[l], 0);

        if (l == 0)
            prep_c5<<<(1024 * 512 + 255) / 256, 256, 0, s2>>>(conv5_w, c5h, c5l);
        prep_w<<<(a.Cout * a.Cin + 255) / 256, 256, 0, s2>>>(
            a.W, a.Cin, a.Cout, a.bias, a.g, a.bb, utw, utwh, utwl, tb);
        if (l == 0) {
            gemm_f2<128, 64, 128><<<dim3(2, PTS / 128, 1), 128, 0, s2>>>(
                x, 3, 0, utw, 3, 0, ut, 128, 0, 3);
        } else {
            mma_gemm<<<dim3(2 * a.Cout / 128, PTS / 128, 1), 256, MMA_SMEM, s2>>>(
                xch + a.inOff, xcl + a.inOff, 512, 0,
                utwh, utwl, a.Cin, 0,
                ut, 2 * a.Cout, 0, a.Cin);
        }
        cudaEventRecord(evj[l], s2);

        // main stream: KNN chain
        gemm_sym<<<dim3(36, 1, B_), 256>>>(
            fin, lda, (long long)N_ * lda, inner, N_, (long long)N_ * N_, a.Cin);
        diag_xx<<<32, 256>>>(inner, xxp);
        topk_kernel<<<PTS / 8, 256>>>(inner, xxp, idx);

        // join, then gather
        cudaStreamWaitEvent(0, evj[l], 0);
        int cx = a.Cout / 4;
        int ppb = 1024 / a.Cout;
        if (ppb > 16) ppb = 16;
        gathermax<<<PTS / ppb, dim3(cx, ppb)>>>(ut, tb, idx, xc, xch, xcl,
                                                a.outOff, a.Cout);
    }

    // conv5 fused with global max-pool (full K=512, on critical path)
    mma_gemm_pool<<<dim3(8, PTS / 128, 1), 256, MMA_SMEM_POOL>>>(
        xch, xcl, 512, c5h, c5l, 512, pool, 512);

    // fused MLP head
    mlp_head<<<B_, 512>>>(pool, lin1_w, bn6_g, bn6_b,
                          lin2_w, lin2_b, bn7_g, bn7_b,
                          lin3_w, lin3_b, (float*)d_out);
}

// round 13
// speedup vs baseline: 1.7302x; 1.1753x over previous
#include <cuda_runtime.h>
#include <cuda_bf16.h>
#include <cstdint>

// DGCNN forward. (R9 configuration — best measured: 362.6us.)
//   edge_conv:  out[b,n,o] = lrelu( max_k ( u[b,idx_k,o] + t[b,n,o] ) )
//   u = (s*W_a)@x ; t = (s*(W_b-W_a))@x + (s*bias + bn_b)
// KNN inner GEMMs: exact fp32 SIMT, symmetric (lower triangle + mirror).
// u|t GEMMs (l2-l4): bf16-split x3 mma.sync. conv5: same, fused with max-pool.
// Side stream carries only the thin [prep_w -> ut GEMM] chain.

#define B_   8
#define N_   1024
#define PTS  (B_ * N_)
#define KNN  20
#define NEG_INF __int_as_float(0xff800000)

__device__ static float          g_xc[PTS * 512];
__device__ static __nv_bfloat16  g_xch[PTS * 512];
__device__ static __nv_bfloat16  g_xcl[PTS * 512];
__device__ static float          g_inner[PTS * 1024];
__device__ static float          g_ut[PTS * 512];
__device__ static float          g_utw[512 * 128];
__device__ static __nv_bfloat16  g_utwh[512 * 128];
__device__ static __nv_bfloat16  g_utwl[512 * 128];
__device__ static __nv_bfloat16  g_c5h[1024 * 512];
__device__ static __nv_bfloat16  g_c5l[1024 * 512];
__device__ static float          g_tb[256];
__device__ static float          g_xx[PTS];
__device__ static int            g_idx[PTS * KNN];
__device__ static unsigned       g_pool[B_ * 1024];
__device__ static float          g_y1[B_ * 512];
__device__ static float          g_y2[B_ * 256];

__device__ __forceinline__ uint32_t smem_u32(const void* p) {
    uint32_t a;
    asm("{ .reg .u64 t; cvta.to.shared.u64 t, %1; cvt.u32.u64 %0, t; }"
        : "=r"(a) : "l"(p));
    return a;
}

__device__ __forceinline__ unsigned redux_max(unsigned v) {
    unsigned r;
    asm("redux.sync.max.u32 %0, %1, 0xffffffff;" : "=r"(r) : "r"(v));
    return r;
}

__device__ __forceinline__ unsigned fenc(float v) {
    unsigned u = __float_as_uint(v);
    return u ^ (((unsigned)((int)u >> 31)) | 0x80000000u);
}

#define LDSM_X4(r0, r1, r2, r3, addr) \
    asm volatile("ldmatrix.sync.aligned.m8n8.x4.shared.b16 {%0,%1,%2,%3}, [%4];" \
                 : "=r"(r0), "=r"(r1), "=r"(r2), "=r"(r3) : "r"(addr))

#define MMA_BF16(c, a, b0, b1) \
    asm volatile( \
        "mma.sync.aligned.m16n8k16.row.col.f32.bf16.bf16.f32 " \
        "{%0,%1,%2,%3}, {%4,%5,%6,%7}, {%8,%9}, {%0,%1,%2,%3};" \
        : "+f"((c)[0]), "+f"((c)[1]), "+f"((c)[2]), "+f"((c)[3]) \
        : "r"((a)[0]), "r"((a)[1]), "r"((a)[2]), "r"((a)[3]), \
          "r"(b0), "r"(b1))

// ---------------------------------------------------------------------------
// bf16-split mma.sync GEMM mainloop (shared)
// ---------------------------------------------------------------------------
#define SKA       40
#define TILE_B    (128 * SKA * 2)
#define STAGE_B   (4 * TILE_B)
#define MMA_SMEM  (2 * STAGE_B)
#define MMA_SMEM_POOL (2 * STAGE_B + 512)

struct MmaCtx {
    float acc[4][4][4];
    int m_warp, n_warp, lane;
};

__device__ __forceinline__ void mma_mainloop(
    char* smem, uint32_t sb0, MmaCtx& cx,
    const __nv_bfloat16* Ah, const __nv_bfloat16* Al, int lda, int m0,
    const __nv_bfloat16* Bh, const __nv_bfloat16* Bl, int ldb, int n0, int K)
{
    const int tid  = threadIdx.x;
    const int wid  = tid >> 5;
    const int lane = tid & 31;
    cx.lane = lane;
    cx.m_warp = (wid & 1) * 64;
    cx.n_warp = (wid >> 1) * 32;

    #pragma unroll
    for (int i = 0; i < 4; i++)
        #pragma unroll
        for (int j = 0; j < 4; j++)
            #pragma unroll
            for (int q = 0; q < 4; q++) cx.acc[i][j][q] = 0.f;

    uint4 stg[8];
    auto ldG = [&](int kc) {
        #pragma unroll
        for (int i = 0; i < 8; i++) {
            int u = tid + i * 256;
            int tile = u >> 9;
            int r = (u >> 2) & 127;
            int q = u & 3;
            const __nv_bfloat16* src;
            int ld_, r0;
            if (tile == 0)      { src = Ah; ld_ = lda; r0 = m0; }
            else if (tile == 1) { src = Al; ld_ = lda; r0 = m0; }
            else if (tile == 2) { src = Bh; ld_ = ldb; r0 = n0; }
            else                { src = Bl; ld_ = ldb; r0 = n0; }
            stg[i] = *reinterpret_cast<const uint4*>(
                src + (size_t)(r0 + r) * ld_ + kc + q * 8);
        }
    };
    auto stS = [&](int stage) {
        char* base = smem + stage * STAGE_B;
        #pragma unroll
        for (int i = 0; i < 8; i++) {
            int u = tid + i * 256;
            int tile = u >> 9;
            int r = (u >> 2) & 127;
            int q = u & 3;
            *reinterpret_cast<uint4*>(base + tile * TILE_B + r * (SKA * 2) + q * 16) = stg[i];
        }
    };

    const int nc = K >> 5;
    ldG(0); stS(0);
    __syncthreads();

    for (int c = 0; c < nc; c++) {
        int buf = c & 1;
        if (c + 1 < nc) ldG((c + 1) * 32);

        const uint32_t sb = sb0 + buf * STAGE_B;
        #pragma unroll
        for (int ks = 0; ks < 32; ks += 16) {
            uint32_t ah[4][4], al[4][4], bh[2][4], bl[2][4];
            const uint32_t lrow = (lane & 15);
            const uint32_t lcol = (lane >> 4) * 8;
            #pragma unroll
            for (int mt = 0; mt < 4; mt++) {
                uint32_t off = ((cx.m_warp + mt * 16 + lrow) * SKA + ks + lcol) * 2;
                LDSM_X4(ah[mt][0], ah[mt][1], ah[mt][2], ah[mt][3], sb + off);
                LDSM_X4(al[mt][0], al[mt][1], al[mt][2], al[mt][3], sb + TILE_B + off);
            }
            #pragma unroll
            for (int np = 0; np < 2; np++) {
                uint32_t off = ((cx.n_warp + np * 16 + lrow) * SKA + ks + lcol) * 2;
                LDSM_X4(bh[np][0], bh[np][1], bh[np][2], bh[np][3], sb + 2 * TILE_B + off);
                LDSM_X4(bl[np][0], bl[np][1], bl[np][2], bl[np][3], sb + 3 * TILE_B + off);
            }
            #pragma unroll
            for (int mt = 0; mt < 4; mt++)
                #pragma unroll
                for (int nt = 0; nt < 4; nt++) {
                    int np = nt >> 1, half = nt & 1;
                    MMA_BF16(cx.acc[mt][nt], ah[mt], bh[np][half], bh[np][2 + half]);
                    MMA_BF16(cx.acc[mt][nt], ah[mt], bl[np][half], bl[np][2 + half]);
                    MMA_BF16(cx.acc[mt][nt], al[mt], bh[np][half], bh[np][2 + half]);
                }
        }

        if (c + 1 < nc) stS(buf ^ 1);
        __syncthreads();
    }
}

__global__ void __launch_bounds__(256)
mma_gemm(const __nv_bfloat16* __restrict__ Ah, const __nv_bfloat16* __restrict__ Al,
         int lda, long long sA,
         const __nv_bfloat16* __restrict__ Bh, const __nv_bfloat16* __restrict__ Bl,
         int ldb, long long sB,
         float* __restrict__ C, int ldc, long long sC, int K)
{
    extern __shared__ char smem[];
    const uint32_t sb0 = smem_u32(smem);
    const int bz = blockIdx.z;
    Ah += bz * sA; Al += bz * sA; Bh += bz * sB; Bl += bz * sB; C += bz * sC;
    const int m0 = blockIdx.y * 128;
    const int n0 = blockIdx.x * 128;

    MmaCtx cx;
    mma_mainloop(smem, sb0, cx, Ah, Al, lda, m0, Bh, Bl, ldb, n0, K);

    #pragma unroll
    for (int mt = 0; mt < 4; mt++)
        #pragma unroll
        for (int nt = 0; nt < 4; nt++) {
            int rm = m0 + cx.m_warp + mt * 16 + (cx.lane >> 2);
            int cn = n0 + cx.n_warp + nt * 8 + (cx.lane & 3) * 2;
            *reinterpret_cast<float2*>(&C[(size_t)rm * ldc + cn]) =
                make_float2(cx.acc[mt][nt][0], cx.acc[mt][nt][1]);
            *reinterpret_cast<float2*>(&C[(size_t)(rm + 8) * ldc + cn]) =
                make_float2(cx.acc[mt][nt][2], cx.acc[mt][nt][3]);
        }
}

// conv5 variant: no C store; row-max reduce; atomicMax into pool.
__global__ void __launch_bounds__(256)
mma_gemm_pool(const __nv_bfloat16* __restrict__ Ah, const __nv_bfloat16* __restrict__ Al,
              int lda,
              const __nv_bfloat16* __restrict__ Bh, const __nv_bfloat16* __restrict__ Bl,
              int ldb,
              unsigned* __restrict__ pool, int K)
{
    extern __shared__ char smem[];
    const uint32_t sb0 = smem_u32(smem);
    unsigned* spool = reinterpret_cast<unsigned*>(smem + 2 * STAGE_B);
    const int tid = threadIdx.x;
    if (tid < 128) spool[tid] = 0u;

    const int m0 = blockIdx.y * 128;
    const int n0 = blockIdx.x * 128;
    const int b  = m0 >> 10;

    MmaCtx cx;
    mma_mainloop(smem, sb0, cx, Ah, Al, lda, m0, Bh, Bl, ldb, n0, K);

    #pragma unroll
    for (int nt = 0; nt < 4; nt++)
        #pragma unroll
        for (int j = 0; j < 2; j++) {
            float v = NEG_INF;
            #pragma unroll
            for (int mt = 0; mt < 4; mt++)
                v = fmaxf(v, fmaxf(cx.acc[mt][nt][j], cx.acc[mt][nt][2 + j]));
            v = fmaxf(v, __shfl_xor_sync(0xffffffffu, v, 4));
            v = fmaxf(v, __shfl_xor_sync(0xffffffffu, v, 8));
            v = fmaxf(v, __shfl_xor_sync(0xffffffffu, v, 16));
            if ((cx.lane >> 2) == 0) {
                unsigned uu = __float_as_uint(v);
                uu = (uu >> 31) ? ~uu : (uu | 0x80000000u);
                atomicMax(&spool[cx.n_warp + nt * 8 + (cx.lane & 3) * 2 + j], uu);
            }
        }
    __syncthreads();
    if (tid < 128) atomicMax(&pool[b * 1024 + n0 + tid], spool[tid]);
}

// ---------------------------------------------------------------------------
// fp32 SIMT GEMM machinery (exact path)
// ---------------------------------------------------------------------------
#define FMA_F32X2(d, a, b, c) \
    asm("fma.rn.f32x2 %0, %1, %2, %3;" : "=l"(d) : "l"(a), "l"(b), "l"(c))
__device__ __forceinline__ float f2lo(unsigned long long v) {
    return __uint_as_float((unsigned)(v & 0xffffffffull));
}
__device__ __forceinline__ float f2hi(unsigned long long v) {
    return __uint_as_float((unsigned)(v >> 32));
}

template<int BM, int BN, int TH>
__global__ void __launch_bounds__(TH, 2)
gemm_f2(const float* __restrict__ A, int lda, long long sA,
        const float* __restrict__ B, int ldb, long long sB,
        float* __restrict__ C, int ldc, long long sC, int K)
{
    constexpr int BK = 8;
    constexpr int LA = 2 * BM + 4;
    constexpr int LB = BN + 4;
    constexpr int NX = BN / 8;
    constexpr int NY = BM / 8;
    static_assert(NX * NY == TH, "threads");
    constexpr int CA = (BM * 2) / TH;
    constexpr int CB = (BN * 2) / TH;

    __shared__ float As2[2][BK][LA];
    __shared__ float Bs[2][BK][LB];

    const int bz = blockIdx.z;
    A += bz * sA; B += bz * sB; C += bz * sC;
    const int m0 = blockIdx.y * BM;
    const int n0 = blockIdx.x * BN;
    const int tid = threadIdx.x;
    const int tx = tid % NX;
    const int ty = tid / NX;
    const bool a4 = ((lda & 3) == 0);
    const bool b4 = ((ldb & 3) == 0);

    unsigned long long acc[8][4];
    #pragma unroll
    for (int i = 0; i < 8; i++)
        #pragma unroll
        for (int j = 0; j < 4; j++) acc[i][j] = 0ull;

    float4 stA[CA], stB[CB];
    auto ldGA = [&](int k0) {
        #pragma unroll
        for (int i = 0; i < CA; i++) {
            int f4 = tid + i * TH;
            int row = f4 >> 1, kq = (f4 & 1) << 2;
            int k = k0 + kq;
            const float* p = A + (size_t)(m0 + row) * lda;
            float4 v;
            if (a4 && (k + 3) < K) v = *reinterpret_cast<const float4*>(p + k);
            else {
                v.x = (k     < K) ? p[k]     : 0.f;
                v.y = (k + 1 < K) ? p[k + 1] : 0.f;
                v.z = (k + 2 < K) ? p[k + 2] : 0.f;
                v.w = (k + 3 < K) ? p[k + 3] : 0.f;
            }
            stA[i] = v;
        }
    };
    auto ldGB = [&](int k0) {
        #pragma unroll
        for (int i = 0; i < CB; i++) {
            int f4 = tid + i * TH;
            int row = f4 >> 1, kq = (f4 & 1) << 2;
            int k = k0 + kq;
            const float* p = B + (size_t)(n0 + row) * ldb;
            float4 v;
            if (b4 && (k + 3) < K) v = *reinterpret_cast<const float4*>(p + k);
            else {
                v.x = (k     < K) ? p[k]     : 0.f;
                v.y = (k + 1 < K) ? p[k + 1] : 0.f;
                v.z = (k + 2 < K) ? p[k + 2] : 0.f;
                v.w = (k + 3 < K) ? p[k + 3] : 0.f;
            }
            stB[i] = v;
        }
    };
    auto stS = [&](int buf) {
        #pragma unroll
        for (int i = 0; i < CA; i++) {
            int f4 = tid + i * TH;
            int row = f4 >> 1, kq = (f4 & 1) << 2;
            float vv[4] = {stA[i].x, stA[i].y, stA[i].z, stA[i].w};
            #pragma unroll
            for (int j = 0; j < 4; j++)
                *reinterpret_cast<float2*>(&As2[buf][kq + j][2 * row]) =
                    make_float2(vv[j], vv[j]);
        }
        #pragma unroll
        for (int i = 0; i < CB; i++) {
            int f4 = tid + i * TH;
            int row = f4 >> 1, kq = (f4 & 1) << 2;
            Bs[buf][kq + 0][row] = stB[i].x;
            Bs[buf][kq + 1][row] = stB[i].y;
            Bs[buf][kq + 2][row] = stB[i].z;
            Bs[buf][kq + 3][row] = stB[i].w;
        }
    };

    const int nt = (K + BK - 1) / BK;
    ldGA(0); ldGB(0); stS(0);
    __syncthreads();

    for (int t = 0; t < nt; t++) {
        int buf = t & 1;
        if (t + 1 < nt) { ldGA((t + 1) * BK); ldGB((t + 1) * BK); }
        #pragma unroll
        for (int k = 0; k < BK; k++) {
            ulonglong2 a01 = *reinterpret_cast<const ulonglong2*>(&As2[buf][k][2 * (ty * 4)]);
            ulonglong2 a23 = *reinterpret_cast<const ulonglong2*>(&As2[buf][k][2 * (ty * 4) + 4]);
            ulonglong2 a45 = *reinterpret_cast<const ulonglong2*>(&As2[buf][k][2 * (BM / 2 + ty * 4)]);
            ulonglong2 a67 = *reinterpret_cast<const ulonglong2*>(&As2[buf][k][2 * (BM / 2 + ty * 4) + 4]);
            ulonglong2 b01 = *reinterpret_cast<const ulonglong2*>(&Bs[buf][k][tx * 4]);
            ulonglong2 b23 = *reinterpret_cast<const ulonglong2*>(&Bs[buf][k][BN / 2 + tx * 4]);
            unsigned long long av[8] = {a01.x, a01.y, a23.x, a23.y,
                                        a45.x, a45.y, a67.x, a67.y};
            unsigned long long bv[4] = {b01.x, b01.y, b23.x, b23.y};
            #pragma unroll
            for (int i = 0; i < 8; i++)
                #pragma unroll
                for (int j = 0; j < 4; j++)
                    FMA_F32X2(acc[i][j], av[i], bv[j], acc[i][j]);
        }
        if (t + 1 < nt) stS(buf ^ 1);
        __syncthreads();
    }

    #pragma unroll
    for (int i = 0; i < 8; i++) {
        int m = m0 + ((i < 4) ? (ty * 4 + i) : (BM / 2 + ty * 4 + i - 4));
        float4 o0, o1;
        o0.x = f2lo(acc[i][0]); o0.y = f2hi(acc[i][0]);
        o0.z = f2lo(acc[i][1]); o0.w = f2hi(acc[i][1]);
        o1.x = f2lo(acc[i][2]); o1.y = f2hi(acc[i][2]);
        o1.z = f2lo(acc[i][3]); o1.w = f2hi(acc[i][3]);
        *reinterpret_cast<float4*>(&C[(size_t)m * ldc + n0 + tx * 4]) = o0;
        *reinterpret_cast<float4*>(&C[(size_t)m * ldc + n0 + BN / 2 + tx * 4]) = o1;
    }
}

// ---------------------------------------------------------------------------
// Symmetric fp32 GEMM: C = X.X^T per batch (lower triangle + mirror store).
// ---------------------------------------------------------------------------
__global__ void __launch_bounds__(256, 2)
gemm_sym(const float* __restrict__ X, int lda, long long sX,
         float* __restrict__ C, int ldc, long long sC, int K)
{
    constexpr int BM = 128, BN = 128, BK = 8;
    constexpr int LA = 2 * BM + 4;
    constexpr int LB = BN + 4;
    constexpr int NX = BN / 8;

    __shared__ float As2[2][BK][LA];
    __shared__ float Bs[2][BK][LB];

    int t = blockIdx.x;
    int i_ = (int)((sqrtf(8.f * t + 1.f) - 1.f) * 0.5f);
    while ((i_ + 1) * (i_ + 2) / 2 <= t) i_++;
    while (i_ * (i_ + 1) / 2 > t) i_--;
    int j_ = t - i_ * (i_ + 1) / 2;

    const int bz = blockIdx.z;
    const float* A = X + bz * sX;
    float* Cb = C + bz * sC;
    const int m0 = i_ * BM;
    const int n0 = j_ * BN;
    const int tid = threadIdx.x;
    const int tx = tid % NX;
    const int ty = tid / NX;
    const bool a4 = ((lda & 3) == 0);

    unsigned long long acc[8][4];
    #pragma unroll
    for (int i = 0; i < 8; i++)
        #pragma unroll
        for (int j = 0; j < 4; j++) acc[i][j] = 0ull;

    float4 stA[1], stB[1];
    auto ldGA = [&](int k0) {
        int row = tid >> 1, kq = (tid & 1) << 2;
        int k = k0 + kq;
        const float* p = A + (size_t)(m0 + row) * lda;
        float4 v;
        if (a4 && (k + 3) < K) v = *reinterpret_cast<const float4*>(p + k);
        else {
            v.x = (k     < K) ? p[k]     : 0.f;
            v.y = (k + 1 < K) ? p[k + 1] : 0.f;
            v.z = (k + 2 < K) ? p[k + 2] : 0.f;
            v.w = (k + 3 < K) ? p[k + 3] : 0.f;
        }
        stA[0] = v;
    };
    auto ldGB = [&](int k0) {
        int row = tid >> 1, kq = (tid & 1) << 2;
        int k = k0 + kq;
        const float* p = A + (size_t)(n0 + row) * lda;
        float4 v;
        if (a4 && (k + 3) < K) v = *reinterpret_cast<const float4*>(p + k);
        else {
            v.x = (k     < K) ? p[k]     : 0.f;
            v.y = (k + 1 < K) ? p[k + 1] : 0.f;
            v.z = (k + 2 < K) ? p[k + 2] : 0.f;
            v.w = (k + 3 < K) ? p[k + 3] : 0.f;
        }
        stB[0] = v;
    };
    auto stS = [&](int buf) {
        int row = tid >> 1, kq = (tid & 1) << 2;
        float vv[4] = {stA[0].x, stA[0].y, stA[0].z, stA[0].w};
        #pragma unroll
        for (int j = 0; j < 4; j++)
            *reinterpret_cast<float2*>(&As2[buf][kq + j][2 * row]) =
                make_float2(vv[j], vv[j]);
        Bs[buf][kq + 0][row] = stB[0].x;
        Bs[buf][kq + 1][row] = stB[0].y;
        Bs[buf][kq + 2][row] = stB[0].z;
        Bs[buf][kq + 3][row] = stB[0].w;
    };

    const int nt = (K + BK - 1) / BK;
    ldGA(0); ldGB(0); stS(0);
    __syncthreads();

    for (int tt = 0; tt < nt; tt++) {
        int buf = tt & 1;
        if (tt + 1 < nt) { ldGA((tt + 1) * BK); ldGB((tt + 1) * BK); }
        #pragma unroll
        for (int k = 0; k < BK; k++) {
            ulonglong2 a01 = *reinterpret_cast<const ulonglong2*>(&As2[buf][k][2 * (ty * 4)]);
            ulonglong2 a23 = *reinterpret_cast<const ulonglong2*>(&As2[buf][k][2 * (ty * 4) + 4]);
            ulonglong2 a45 = *reinterpret_cast<const ulonglong2*>(&As2[buf][k][2 * (BM / 2 + ty * 4)]);
            ulonglong2 a67 = *reinterpret_cast<const ulonglong2*>(&As2[buf][k][2 * (BM / 2 + ty * 4) + 4]);
            ulonglong2 b01 = *reinterpret_cast<const ulonglong2*>(&Bs[buf][k][tx * 4]);
            ulonglong2 b23 = *reinterpret_cast<const ulonglong2*>(&Bs[buf][k][BN / 2 + tx * 4]);
            unsigned long long av[8] = {a01.x, a01.y, a23.x, a23.y,
                                        a45.x, a45.y, a67.x, a67.y};
            unsigned long long bv[4] = {b01.x, b01.y, b23.x, b23.y};
            #pragma unroll
            for (int i = 0; i < 8; i++)
                #pragma unroll
                for (int j = 0; j < 4; j++)
                    FMA_F32X2(acc[i][j], av[i], bv[j], acc[i][j]);
        }
        if (tt + 1 < nt) stS(buf ^ 1);
        __syncthreads();
    }

    float f[8][8];
    int mrow[8], ncol[8];
    #pragma unroll
    for (int i = 0; i < 8; i++) {
        mrow[i] = m0 + ((i < 4) ? (ty * 4 + i) : (64 + ty * 4 + i - 4));
        ncol[i] = n0 + ((i < 4) ? (tx * 4 + i) : (64 + tx * 4 + i - 4));
        f[i][0] = f2lo(acc[i][0]); f[i][1] = f2hi(acc[i][0]);
        f[i][2] = f2lo(acc[i][1]); f[i][3] = f2hi(acc[i][1]);
        f[i][4] = f2lo(acc[i][2]); f[i][5] = f2hi(acc[i][2]);
        f[i][6] = f2lo(acc[i][3]); f[i][7] = f2hi(acc[i][3]);
    }

    #pragma unroll
    for (int i = 0; i < 8; i++) {
        *reinterpret_cast<float4*>(&Cb[(size_t)mrow[i] * ldc + ncol[0]]) =
            make_float4(f[i][0], f[i][1], f[i][2], f[i][3]);
        *reinterpret_cast<float4*>(&Cb[(size_t)mrow[i] * ldc + ncol[4]]) =
            make_float4(f[i][4], f[i][5], f[i][6], f[i][7]);
    }
    if (i_ != j_) {
        #pragma unroll
        for (int q = 0; q < 8; q++) {
            *reinterpret_cast<float4*>(&Cb[(size_t)ncol[q] * ldc + mrow[0]]) =
                make_float4(f[0][q], f[1][q], f[2][q], f[3][q]);
            *reinterpret_cast<float4*>(&Cb[(size_t)ncol[q] * ldc + mrow[4]]) =
                make_float4(f[4][q], f[5][q], f[6][q], f[7][q]);
        }
    }
}

// ---------------------------------------------------------------------------
__global__ void diag_xx(const float* __restrict__ inner, float* __restrict__ xx)
{
    int p = blockIdx.x * 256 + threadIdx.x;
    if (p < PTS) xx[p] = inner[(size_t)p * N_ + (p & (N_ - 1))];
}

// ---------------------------------------------------------------------------
// top-20: warp per row, float4 scan, u32 key top-2 cache + index regs,
// pops via redux.sync.max.u32 pair.
// ---------------------------------------------------------------------------
__device__ __forceinline__ void tk_upd(unsigned& k1, unsigned& m1,
                                       unsigned& k2, unsigned& m2,
                                       unsigned e, unsigned m) {
    if (e > k1)      { k2 = k1; m2 = m1; k1 = e; m1 = m; }
    else if (e > k2) { k2 = e; m2 = m; }
}

__global__ void __launch_bounds__(256)
topk_kernel(const float* __restrict__ inner, const float* __restrict__ xx,
            int* __restrict__ idx_out)
{
    __shared__ uint4 s4[8][N_ / 4];
    int wid  = threadIdx.x >> 5;
    int lane = threadIdx.x & 31;
    int row  = blockIdx.x * 8 + wid;
    int b    = row >> 10;
    uint4* sw4 = s4[wid];
    unsigned* sw = reinterpret_cast<unsigned*>(sw4);
    const float4* r4 = reinterpret_cast<const float4*>(inner + (size_t)row * N_);
    const float4* x4 = reinterpret_cast<const float4*>(xx + (b << 10));

    unsigned k1 = 0, m1 = 0, k2 = 0, m2 = 0;
    #pragma unroll
    for (int i = 0; i < 8; i++) {
        int q = i * 32 + lane;
        float4 rv = r4[q];
        float4 xv = x4[q];
        unsigned mb = (unsigned)q * 4;
        unsigned e0 = fenc(fmaf(2.f, rv.x, -xv.x));
        unsigned e1 = fenc(fmaf(2.f, rv.y, -xv.y));
        unsigned e2 = fenc(fmaf(2.f, rv.z, -xv.z));
        unsigned e3 = fenc(fmaf(2.f, rv.w, -xv.w));
        sw4[q] = make_uint4(e0, e1, e2, e3);
        tk_upd(k1, m1, k2, m2, e0, mb);
        tk_upd(k1, m1, k2, m2, e1, mb + 1);
        tk_upd(k1, m1, k2, m2, e2, mb + 2);
        tk_upd(k1, m1, k2, m2, e3, mb + 3);
    }
    __syncwarp();

    for (int it = 0; it < KNN; it++) {
        unsigned wkey = redux_max(k1);
        unsigned cand = (k1 == wkey) ? (1023u - m1) : 0u;
        unsigned widx = redux_max(cand);
        unsigned m = 1023u - widx;
        if (lane == 0) idx_out[row * KNN + it] = (int)m;
        if (k1 == wkey && (1023u - m1) == widx) {
            sw[m] = 0;
            k1 = k2; m1 = m2; k2 = 0; m2 = 0;
            if (k1 == 0) {
                #pragma unroll
                for (int i = 0; i < 8; i++) {
                    int q = i * 32 + lane;
                    uint4 v = sw4[q];
                    unsigned mb = (unsigned)q * 4;
                    tk_upd(k1, m1, k2, m2, v.x, mb);
                    tk_upd(k1, m1, k2, m2, v.y, mb + 1);
                    tk_upd(k1, m1, k2, m2, v.z, mb + 2);
                    tk_upd(k1, m1, k2, m2, v.w, mb + 3);
                }
            }
        }
        __syncwarp();
    }
}

// ---------------------------------------------------------------------------
__device__ __forceinline__ void split_store(float v, __nv_bfloat16* h, __nv_bfloat16* l,
                                            size_t i)
{
    __nv_bfloat16 hb = __float2bfloat16(v);
    h[i] = hb;
    l[i] = __float2bfloat16(v - __bfloat162float(hb));
}

__global__ void prep_w(const float* __restrict__ W, int C, int O,
                       const float* __restrict__ bias,
                       const float* __restrict__ bng, const float* __restrict__ bnb,
                       float* __restrict__ utw,
                       __nv_bfloat16* __restrict__ utwh, __nv_bfloat16* __restrict__ utwl,
                       float* __restrict__ tb)
{
    const float inv = 1.0f / sqrtf(1.00001f);
    int i = blockIdx.x * 256 + threadIdx.x;
    if (i < O * C) {
        int o = i / C, c = i - o * C;
        float s = bng[o] * inv;
        float wa = W[o * 2 * C + c];
        float wb = W[o * 2 * C + C + c];
        float vu = s * wa;
        float vt = s * (wb - wa);
        utw[(size_t)o * C + c] = vu;
        utw[(size_t)(O + o) * C + c] = vt;
        split_store(vu, utwh, utwl, (size_t)o * C + c);
        split_store(vt, utwh, utwl, (size_t)(O + o) * C + c);
    }
    if (i < O) {
        float s = bng[i] * inv;
        tb[i] = s * (bias ? bias[i] : 0.f) + bnb[i];
    }
}

__global__ void prep_c5(const float* __restrict__ W,
                        __nv_bfloat16* __restrict__ h, __nv_bfloat16* __restrict__ l)
{
    int i = blockIdx.x * 256 + threadIdx.x;
    if (i < 1024 * 512) split_store(W[i], h, l, i);
}

// ---------------------------------------------------------------------------
__global__ void gathermax(const float* __restrict__ ut, const float* __restrict__ tb,
                          const int* __restrict__ idx,
                          float* __restrict__ xc,
                          __nv_bfloat16* __restrict__ xch, __nv_bfloat16* __restrict__ xcl,
                          int colOff, int CO)
{
    __shared__ int sidx[16][KNN];
    int ty = threadIdx.y, tx = threadIdx.x;
    int p = blockIdx.x * blockDim.y + ty;
    int b = p >> 10;
    for (int k = tx; k < KNN; k += blockDim.x) sidx[ty][k] = idx[p * KNN + k];
    __syncthreads();

    int st = 2 * CO;
    float4 tv = *reinterpret_cast<const float4*>(ut + (size_t)p * st + CO + tx * 4);
    float4 bv = *reinterpret_cast<const float4*>(tb + tx * 4);
    tv.x += bv.x; tv.y += bv.y; tv.z += bv.z; tv.w += bv.w;

    float4 mx = make_float4(NEG_INF, NEG_INF, NEG_INF, NEG_INF);
    #pragma unroll 4
    for (int k = 0; k < KNN; k++) {
        int j = sidx[ty][k];
        float4 v = *reinterpret_cast<const float4*>(
            ut + (size_t)((b << 10) + j) * st + tx * 4);
        mx.x = fmaxf(mx.x, v.x + tv.x);
        mx.y = fmaxf(mx.y, v.y + tv.y);
        mx.z = fmaxf(mx.z, v.z + tv.z);
        mx.w = fmaxf(mx.w, v.w + tv.w);
    }
    mx.x = (mx.x >= 0.f) ? mx.x : 0.01f * mx.x;
    mx.y = (mx.y >= 0.f) ? mx.y : 0.01f * mx.y;
    mx.z = (mx.z >= 0.f) ? mx.z : 0.01f * mx.z;
    mx.w = (mx.w >= 0.f) ? mx.w : 0.01f * mx.w;

    size_t o = (size_t)p * 512 + colOff + tx * 4;
    *reinterpret_cast<float4*>(xc + o) = mx;

    float vals[4] = {mx.x, mx.y, mx.z, mx.w};
    __nv_bfloat16 hb[4], lb[4];
    #pragma unroll
    for (int i = 0; i < 4; i++) {
        hb[i] = __float2bfloat16(vals[i]);
        lb[i] = __float2bfloat16(vals[i] - __bfloat162float(hb[i]));
    }
    *reinterpret_cast<uint2*>(xch + o) = *reinterpret_cast<uint2*>(hb);
    *reinterpret_cast<uint2*>(xcl + o) = *reinterpret_cast<uint2*>(lb);
}

// ---------------------------------------------------------------------------
__global__ void zero_pool(unsigned* pool)
{
    int i = blockIdx.x * 256 + threadIdx.x;
    if (i < B_ * 1024) pool[i] = 0u;
}

__device__ __forceinline__ float dec_pool(unsigned u)
{
    return (u & 0x80000000u) ? __uint_as_float(u & 0x7fffffffu) : __uint_as_float(~u);
}

// ---------------------------------------------------------------------------
__global__ void mlp1(const unsigned* __restrict__ pool, const float* __restrict__ w,
                     const float* __restrict__ g6, const float* __restrict__ b6,
                     float* __restrict__ y1)
{
    int b = blockIdx.y;
    int j = blockIdx.x * 4 + threadIdx.y;
    int lane = threadIdx.x;
    float s = 0.f;
    for (int c = lane; c < 1024; c += 32)
        s += dec_pool(pool[b * 1024 + c]) * w[j * 1024 + c];
    #pragma unroll
    for (int off = 16; off; off >>= 1) s += __shfl_xor_sync(0xffffffffu, s, off);
    if (lane == 0) {
        float v = s * (g6[j] * (1.0f / sqrtf(1.00001f))) + b6[j];
        y1[b * 512 + j] = (v >= 0.f) ? v : 0.01f * v;
    }
}

__global__ void mlp2(const float* __restrict__ y1, const float* __restrict__ w,
                     const float* __restrict__ wb, const float* __restrict__ g7,
                     const float* __restrict__ b7, float* __restrict__ y2)
{
    int b = blockIdx.y;
    int j = blockIdx.x * 4 + threadIdx.y;
    int lane = threadIdx.x;
    float s = 0.f;
    for (int c = lane; c < 512; c += 32) s += y1[b * 512 + c] * w[j * 512 + c];
    #pragma unroll
    for (int off = 16; off; off >>= 1) s += __shfl_xor_sync(0xffffffffu, s, off);
    if (lane == 0) {
        float v = (s + wb[j]) * (g7[j] * (1.0f / sqrtf(1.00001f))) + b7[j];
        y2[b * 256 + j] = (v >= 0.f) ? v : 0.01f * v;
    }
}

__global__ void mlp3(const float* __restrict__ y2, const float* __restrict__ w,
                     const float* __restrict__ wb, float* __restrict__ out)
{
    int b = blockIdx.y;
    int j = blockIdx.x * 4 + threadIdx.y;
    int lane = threadIdx.x;
    float s = 0.f;
    for (int c = lane; c < 256; c += 32) s += y2[b * 256 + c] * w[j * 256 + c];
    #pragma unroll
    for (int off = 16; off; off >>= 1) s += __shfl_xor_sync(0xffffffffu, s, off);
    if (lane == 0) out[b * 40 + j] = s + wb[j];
}

// ---------------------------------------------------------------------------
extern "C" void kernel_launch(void* const* d_in, const int* in_sizes, int n_in,
                              void* d_out, int out_size)
{
    const float* x        = (const float*)d_in[0];
    const float* conv1_w  = (const float*)d_in[1];
    const float* conv1_b  = (const float*)d_in[2];
    const float* bn1_g    = (const float*)d_in[3];
    const float* bn1_b    = (const float*)d_in[4];
    const float* conv2_w  = (const float*)d_in[5];
    const float* bn2_g    = (const float*)d_in[6];
    const float* bn2_b    = (const float*)d_in[7];
    const float* conv3_w  = (const float*)d_in[8];
    const float* bn3_g    = (const float*)d_in[9];
    const float* bn3_b    = (const float*)d_in[10];
    const float* conv4_w  = (const float*)d_in[11];
    const float* bn4_g    = (const float*)d_in[12];
    const float* bn4_b    = (const float*)d_in[13];
    const float* conv5_w  = (const float*)d_in[14];
    const float* lin1_w   = (const float*)d_in[15];
    const float* bn6_g    = (const float*)d_in[16];
    const float* bn6_b    = (const float*)d_in[17];
    const float* lin2_w   = (const float*)d_in[18];
    const float* lin2_b   = (const float*)d_in[19];
    const float* bn7_g    = (const float*)d_in[20];
    const float* bn7_b    = (const float*)d_in[21];
    const float* lin3_w   = (const float*)d_in[22];
    const float* lin3_b   = (const float*)d_in[23];

    float *xc, *inner, *ut, *utw, *tb, *xxp, *y1, *y2;
    __nv_bfloat16 *xch, *xcl, *utwh, *utwl, *c5h, *c5l;
    int* idx; unsigned* pool;
    cudaGetSymbolAddress((void**)&xc,    g_xc);
    cudaGetSymbolAddress((void**)&inner, g_inner);
    cudaGetSymbolAddress((void**)&xch,   g_xch);
    cudaGetSymbolAddress((void**)&xcl,   g_xcl);
    cudaGetSymbolAddress((void**)&ut,    g_ut);
    cudaGetSymbolAddress((void**)&utw,   g_utw);
    cudaGetSymbolAddress((void**)&utwh,  g_utwh);
    cudaGetSymbolAddress((void**)&utwl,  g_utwl);
    cudaGetSymbolAddress((void**)&c5h,   g_c5h);
    cudaGetSymbolAddress((void**)&c5l,   g_c5l);
    cudaGetSymbolAddress((void**)&tb,    g_tb);
    cudaGetSymbolAddress((void**)&xxp,   g_xx);
    cudaGetSymbolAddress((void**)&idx,   g_idx);
    cudaGetSymbolAddress((void**)&pool,  g_pool);
    cudaGetSymbolAddress((void**)&y1,    g_y1);
    cudaGetSymbolAddress((void**)&y2,    g_y2);

    cudaFuncSetAttribute(mma_gemm, cudaFuncAttributeMaxDynamicSharedMemorySize, MMA_SMEM);
    cudaFuncSetAttribute(mma_gemm_pool, cudaFuncAttributeMaxDynamicSharedMemorySize,
                         MMA_SMEM_POOL);

    static cudaStream_t s2 = nullptr;
    static cudaEvent_t evf[4], evj[4];
    if (s2 == nullptr) {
        cudaStreamCreateWithFlags(&s2, cudaStreamNonBlocking);
        for (int i = 0; i < 4; i++) {
            cudaEventCreateWithFlags(&evf[i], cudaEventDisableTiming);
            cudaEventCreateWithFlags(&evj[i], cudaEventDisableTiming);
        }
    }

    struct Layer {
        int inOff; int Cin; int Cout; int outOff;
        const float* W; const float* bias; const float* g; const float* bb;
    };
    Layer L[4] = {
        { -1,  3,   64,  0,   conv1_w, conv1_b, bn1_g, bn1_b },
        { 0,   64,  64,  64,  conv2_w, nullptr, bn2_g, bn2_b },
        { 64,  64,  128, 128, conv3_w, nullptr, bn3_g, bn3_b },
        { 128, 128, 256, 256, conv4_w, nullptr, bn4_g, bn4_b },
    };

    zero_pool<<<32, 256>>>(pool);

    for (int l = 0; l < 4; l++) {
        const Layer& a = L[l];
        const float* fin = (l == 0) ? x : (xc + a.inOff);
        int lda = (l == 0) ? 3 : 512;

        // fork: side stream computes the thin [prep -> u|t GEMM] chain
        cudaEventRecord(evf[l], 0);
        cudaStreamWaitEvent(s2, evf[l], 0);

        if (l == 0)
            prep_c5<<<(1024 * 512 + 255) / 256, 256, 0, s2>>>(conv5_w, c5h, c5l);
        prep_w<<<(a.Cout * a.Cin + 255) / 256, 256, 0, s2>>>(
            a.W, a.Cin, a.Cout, a.bias, a.g, a.bb, utw, utwh, utwl, tb);
        if (l == 0) {
            gemm_f2<128, 64, 128><<<dim3(2, PTS / 128, 1), 128, 0, s2>>>(
                x, 3, 0, utw, 3, 0, ut, 128, 0, 3);
        } else {
            mma_gemm<<<dim3(2 * a.Cout / 128, PTS / 128, 1), 256, MMA_SMEM, s2>>>(
                xch + a.inOff, xcl + a.inOff, 512, 0,
                utwh, utwl, a.Cin, 0,
                ut, 2 * a.Cout, 0, a.Cin);
        }
        cudaEventRecord(evj[l], s2);

        // main stream: KNN chain
        gemm_sym<<<dim3(36, 1, B_), 256>>>(
            fin, lda, (long long)N_ * lda, inner, N_, (long long)N_ * N_, a.Cin);
        diag_xx<<<32, 256>>>(inner, xxp);
        topk_kernel<<<PTS / 8, 256>>>(inner, xxp, idx);

        // join, then gather
        cudaStreamWaitEvent(0, evj[l], 0);
        int cx = a.Cout / 4;
        int ppb = 1024 / a.Cout;
        if (ppb > 16) ppb = 16;
        gathermax<<<PTS / ppb, dim3(cx, ppb)>>>(ut, tb, idx, xc, xch, xcl,
                                                a.outOff, a.Cout);
    }

    // conv5 fused with global max-pool
    mma_gemm_pool<<<dim3(8, PTS / 128, 1), 256, MMA_SMEM_POOL>>>(
        xch, xcl, 512, c5h, c5l, 512, pool, 512);

    // MLP head (separate wide-grid kernels: weight reads spread over many CTAs)
    mlp1<<<dim3(128, B_), dim3(32, 4)>>>(pool, lin1_w, bn6_g, bn6_b, y1);
    mlp2<<<dim3(64, B_),  dim3(32, 4)>>>(y1, lin2_w, lin2_b, bn7_g, bn7_b, y2);
    mlp3<<<dim3(10, B_),  dim3(32, 4)>>>(y2, lin3_w, lin3_b, (float*)d_out);
}

// round 14
// speedup vs baseline: 1.7677x; 1.0216x over previous
#include <cuda_runtime.h>
#include <cuda_bf16.h>
#include <cstdint>

// DGCNN forward. (R9/R13 structure; diag_xx folded into gemm_sym epilogue.)
//   edge_conv:  out[b,n,o] = lrelu( max_k ( u[b,idx_k,o] + t[b,n,o] ) )
//   u = (s*W_a)@x ; t = (s*(W_b-W_a))@x + (s*bias + bn_b)
// KNN inner GEMMs: exact fp32 SIMT, symmetric (lower triangle + mirror);
// diagonal tiles also emit xx[p] = inner[p][p] (bit-identical to old diag_xx).
// u|t GEMMs (l2-l4): bf16-split x3 mma.sync. conv5: same, fused with max-pool.
// Side stream carries only the thin [prep_w -> ut GEMM] chain.

#define B_   8
#define N_   1024
#define PTS  (B_ * N_)
#define KNN  20
#define NEG_INF __int_as_float(0xff800000)

__device__ static float          g_xc[PTS * 512];
__device__ static __nv_bfloat16  g_xch[PTS * 512];
__device__ static __nv_bfloat16  g_xcl[PTS * 512];
__device__ static float          g_inner[PTS * 1024];
__device__ static float          g_ut[PTS * 512];
__device__ static float          g_utw[512 * 128];
__device__ static __nv_bfloat16  g_utwh[512 * 128];
__device__ static __nv_bfloat16  g_utwl[512 * 128];
__device__ static __nv_bfloat16  g_c5h[1024 * 512];
__device__ static __nv_bfloat16  g_c5l[1024 * 512];
__device__ static float          g_tb[256];
__device__ static float          g_xx[PTS];
__device__ static int            g_idx[PTS * KNN];
__device__ static unsigned       g_pool[B_ * 1024];
__device__ static float          g_y1[B_ * 512];
__device__ static float          g_y2[B_ * 256];

__device__ __forceinline__ uint32_t smem_u32(const void* p) {
    uint32_t a;
    asm("{ .reg .u64 t; cvta.to.shared.u64 t, %1; cvt.u32.u64 %0, t; }"
        : "=r"(a) : "l"(p));
    return a;
}

__device__ __forceinline__ unsigned redux_max(unsigned v) {
    unsigned r;
    asm("redux.sync.max.u32 %0, %1, 0xffffffff;" : "=r"(r) : "r"(v));
    return r;
}

__device__ __forceinline__ unsigned fenc(float v) {
    unsigned u = __float_as_uint(v);
    return u ^ (((unsigned)((int)u >> 31)) | 0x80000000u);
}

#define LDSM_X4(r0, r1, r2, r3, addr) \
    asm volatile("ldmatrix.sync.aligned.m8n8.x4.shared.b16 {%0,%1,%2,%3}, [%4];" \
                 : "=r"(r0), "=r"(r1), "=r"(r2), "=r"(r3) : "r"(addr))

#define MMA_BF16(c, a, b0, b1) \
    asm volatile( \
        "mma.sync.aligned.m16n8k16.row.col.f32.bf16.bf16.f32 " \
        "{%0,%1,%2,%3}, {%4,%5,%6,%7}, {%8,%9}, {%0,%1,%2,%3};" \
        : "+f"((c)[0]), "+f"((c)[1]), "+f"((c)[2]), "+f"((c)[3]) \
        : "r"((a)[0]), "r"((a)[1]), "r"((a)[2]), "r"((a)[3]), \
          "r"(b0), "r"(b1))

// ---------------------------------------------------------------------------
// bf16-split mma.sync GEMM mainloop (shared)
// ---------------------------------------------------------------------------
#define SKA       40
#define TILE_B    (128 * SKA * 2)
#define STAGE_B   (4 * TILE_B)
#define MMA_SMEM  (2 * STAGE_B)
#define MMA_SMEM_POOL (2 * STAGE_B + 512)

struct MmaCtx {
    float acc[4][4][4];
    int m_warp, n_warp, lane;
};

__device__ __forceinline__ void mma_mainloop(
    char* smem, uint32_t sb0, MmaCtx& cx,
    const __nv_bfloat16* Ah, const __nv_bfloat16* Al, int lda, int m0,
    const __nv_bfloat16* Bh, const __nv_bfloat16* Bl, int ldb, int n0, int K)
{
    const int tid  = threadIdx.x;
    const int wid  = tid >> 5;
    const int lane = tid & 31;
    cx.lane = lane;
    cx.m_warp = (wid & 1) * 64;
    cx.n_warp = (wid >> 1) * 32;

    #pragma unroll
    for (int i = 0; i < 4; i++)
        #pragma unroll
        for (int j = 0; j < 4; j++)
            #pragma unroll
            for (int q = 0; q < 4; q++) cx.acc[i][j][q] = 0.f;

    uint4 stg[8];
    auto ldG = [&](int kc) {
        #pragma unroll
        for (int i = 0; i < 8; i++) {
            int u = tid + i * 256;
            int tile = u >> 9;
            int r = (u >> 2) & 127;
            int q = u & 3;
            const __nv_bfloat16* src;
            int ld_, r0;
            if (tile == 0)      { src = Ah; ld_ = lda; r0 = m0; }
            else if (tile == 1) { src = Al; ld_ = lda; r0 = m0; }
            else if (tile == 2) { src = Bh; ld_ = ldb; r0 = n0; }
            else                { src = Bl; ld_ = ldb; r0 = n0; }
            stg[i] = *reinterpret_cast<const uint4*>(
                src + (size_t)(r0 + r) * ld_ + kc + q * 8);
        }
    };
    auto stS = [&](int stage) {
        char* base = smem + stage * STAGE_B;
        #pragma unroll
        for (int i = 0; i < 8; i++) {
            int u = tid + i * 256;
            int tile = u >> 9;
            int r = (u >> 2) & 127;
            int q = u & 3;
            *reinterpret_cast<uint4*>(base + tile * TILE_B + r * (SKA * 2) + q * 16) = stg[i];
        }
    };

    const int nc = K >> 5;
    ldG(0); stS(0);
    __syncthreads();

    for (int c = 0; c < nc; c++) {
        int buf = c & 1;
        if (c + 1 < nc) ldG((c + 1) * 32);

        const uint32_t sb = sb0 + buf * STAGE_B;
        #pragma unroll
        for (int ks = 0; ks < 32; ks += 16) {
            uint32_t ah[4][4], al[4][4], bh[2][4], bl[2][4];
            const uint32_t lrow = (lane & 15);
            const uint32_t lcol = (lane >> 4) * 8;
            #pragma unroll
            for (int mt = 0; mt < 4; mt++) {
                uint32_t off = ((cx.m_warp + mt * 16 + lrow) * SKA + ks + lcol) * 2;
                LDSM_X4(ah[mt][0], ah[mt][1], ah[mt][2], ah[mt][3], sb + off);
                LDSM_X4(al[mt][0], al[mt][1], al[mt][2], al[mt][3], sb + TILE_B + off);
            }
            #pragma unroll
            for (int np = 0; np < 2; np++) {
                uint32_t off = ((cx.n_warp + np * 16 + lrow) * SKA + ks + lcol) * 2;
                LDSM_X4(bh[np][0], bh[np][1], bh[np][2], bh[np][3], sb + 2 * TILE_B + off);
                LDSM_X4(bl[np][0], bl[np][1], bl[np][2], bl[np][3], sb + 3 * TILE_B + off);
            }
            #pragma unroll
            for (int mt = 0; mt < 4; mt++)
                #pragma unroll
                for (int nt = 0; nt < 4; nt++) {
                    int np = nt >> 1, half = nt & 1;
                    MMA_BF16(cx.acc[mt][nt], ah[mt], bh[np][half], bh[np][2 + half]);
                    MMA_BF16(cx.acc[mt][nt], ah[mt], bl[np][half], bl[np][2 + half]);
                    MMA_BF16(cx.acc[mt][nt], al[mt], bh[np][half], bh[np][2 + half]);
                }
        }

        if (c + 1 < nc) stS(buf ^ 1);
        __syncthreads();
    }
}

__global__ void __launch_bounds__(256)
mma_gemm(const __nv_bfloat16* __restrict__ Ah, const __nv_bfloat16* __restrict__ Al,
         int lda, long long sA,
         const __nv_bfloat16* __restrict__ Bh, const __nv_bfloat16* __restrict__ Bl,
         int ldb, long long sB,
         float* __restrict__ C, int ldc, long long sC, int K)
{
    extern __shared__ char smem[];
    const uint32_t sb0 = smem_u32(smem);
    const int bz = blockIdx.z;
    Ah += bz * sA; Al += bz * sA; Bh += bz * sB; Bl += bz * sB; C += bz * sC;
    const int m0 = blockIdx.y * 128;
    const int n0 = blockIdx.x * 128;

    MmaCtx cx;
    mma_mainloop(smem, sb0, cx, Ah, Al, lda, m0, Bh, Bl, ldb, n0, K);

    #pragma unroll
    for (int mt = 0; mt < 4; mt++)
        #pragma unroll
        for (int nt = 0; nt < 4; nt++) {
            int rm = m0 + cx.m_warp + mt * 16 + (cx.lane >> 2);
            int cn = n0 + cx.n_warp + nt * 8 + (cx.lane & 3) * 2;
            *reinterpret_cast<float2*>(&C[(size_t)rm * ldc + cn]) =
                make_float2(cx.acc[mt][nt][0], cx.acc[mt][nt][1]);
            *reinterpret_cast<float2*>(&C[(size_t)(rm + 8) * ldc + cn]) =
                make_float2(cx.acc[mt][nt][2], cx.acc[mt][nt][3]);
        }
}

// conv5 variant: no C store; row-max reduce; atomicMax into pool.
__global__ void __launch_bounds__(256)
mma_gemm_pool(const __nv_bfloat16* __restrict__ Ah, const __nv_bfloat16* __restrict__ Al,
              int lda,
              const __nv_bfloat16* __restrict__ Bh, const __nv_bfloat16* __restrict__ Bl,
              int ldb,
              unsigned* __restrict__ pool, int K)
{
    extern __shared__ char smem[];
    const uint32_t sb0 = smem_u32(smem);
    unsigned* spool = reinterpret_cast<unsigned*>(smem + 2 * STAGE_B);
    const int tid = threadIdx.x;
    if (tid < 128) spool[tid] = 0u;

    const int m0 = blockIdx.y * 128;
    const int n0 = blockIdx.x * 128;
    const int b  = m0 >> 10;

    MmaCtx cx;
    mma_mainloop(smem, sb0, cx, Ah, Al, lda, m0, Bh, Bl, ldb, n0, K);

    #pragma unroll
    for (int nt = 0; nt < 4; nt++)
        #pragma unroll
        for (int j = 0; j < 2; j++) {
            float v = NEG_INF;
            #pragma unroll
            for (int mt = 0; mt < 4; mt++)
                v = fmaxf(v, fmaxf(cx.acc[mt][nt][j], cx.acc[mt][nt][2 + j]));
            v = fmaxf(v, __shfl_xor_sync(0xffffffffu, v, 4));
            v = fmaxf(v, __shfl_xor_sync(0xffffffffu, v, 8));
            v = fmaxf(v, __shfl_xor_sync(0xffffffffu, v, 16));
            if ((cx.lane >> 2) == 0) {
                unsigned uu = __float_as_uint(v);
                uu = (uu >> 31) ? ~uu : (uu | 0x80000000u);
                atomicMax(&spool[cx.n_warp + nt * 8 + (cx.lane & 3) * 2 + j], uu);
            }
        }
    __syncthreads();
    if (tid < 128) atomicMax(&pool[b * 1024 + n0 + tid], spool[tid]);
}

// ---------------------------------------------------------------------------
// fp32 SIMT GEMM machinery (exact path)
// ---------------------------------------------------------------------------
#define FMA_F32X2(d, a, b, c) \
    asm("fma.rn.f32x2 %0, %1, %2, %3;" : "=l"(d) : "l"(a), "l"(b), "l"(c))
__device__ __forceinline__ float f2lo(unsigned long long v) {
    return __uint_as_float((unsigned)(v & 0xffffffffull));
}
__device__ __forceinline__ float f2hi(unsigned long long v) {
    return __uint_as_float((unsigned)(v >> 32));
}

template<int BM, int BN, int TH>
__global__ void __launch_bounds__(TH, 2)
gemm_f2(const float* __restrict__ A, int lda, long long sA,
        const float* __restrict__ B, int ldb, long long sB,
        float* __restrict__ C, int ldc, long long sC, int K)
{
    constexpr int BK = 8;
    constexpr int LA = 2 * BM + 4;
    constexpr int LB = BN + 4;
    constexpr int NX = BN / 8;
    constexpr int NY = BM / 8;
    static_assert(NX * NY == TH, "threads");
    constexpr int CA = (BM * 2) / TH;
    constexpr int CB = (BN * 2) / TH;

    __shared__ float As2[2][BK][LA];
    __shared__ float Bs[2][BK][LB];

    const int bz = blockIdx.z;
    A += bz * sA; B += bz * sB; C += bz * sC;
    const int m0 = blockIdx.y * BM;
    const int n0 = blockIdx.x * BN;
    const int tid = threadIdx.x;
    const int tx = tid % NX;
    const int ty = tid / NX;
    const bool a4 = ((lda & 3) == 0);
    const bool b4 = ((ldb & 3) == 0);

    unsigned long long acc[8][4];
    #pragma unroll
    for (int i = 0; i < 8; i++)
        #pragma unroll
        for (int j = 0; j < 4; j++) acc[i][j] = 0ull;

    float4 stA[CA], stB[CB];
    auto ldGA = [&](int k0) {
        #pragma unroll
        for (int i = 0; i < CA; i++) {
            int f4 = tid + i * TH;
            int row = f4 >> 1, kq = (f4 & 1) << 2;
            int k = k0 + kq;
            const float* p = A + (size_t)(m0 + row) * lda;
            float4 v;
            if (a4 && (k + 3) < K) v = *reinterpret_cast<const float4*>(p + k);
            else {
                v.x = (k     < K) ? p[k]     : 0.f;
                v.y = (k + 1 < K) ? p[k + 1] : 0.f;
                v.z = (k + 2 < K) ? p[k + 2] : 0.f;
                v.w = (k + 3 < K) ? p[k + 3] : 0.f;
            }
            stA[i] = v;
        }
    };
    auto ldGB = [&](int k0) {
        #pragma unroll
        for (int i = 0; i < CB; i++) {
            int f4 = tid + i * TH;
            int row = f4 >> 1, kq = (f4 & 1) << 2;
            int k = k0 + kq;
            const float* p = B + (size_t)(n0 + row) * ldb;
            float4 v;
            if (b4 && (k + 3) < K) v = *reinterpret_cast<const float4*>(p + k);
            else {
                v.x = (k     < K) ? p[k]     : 0.f;
                v.y = (k + 1 < K) ? p[k + 1] : 0.f;
                v.z = (k + 2 < K) ? p[k + 2] : 0.f;
                v.w = (k + 3 < K) ? p[k + 3] : 0.f;
            }
            stB[i] = v;
        }
    };
    auto stS = [&](int buf) {
        #pragma unroll
        for (int i = 0; i < CA; i++) {
            int f4 = tid + i * TH;
            int row = f4 >> 1, kq = (f4 & 1) << 2;
            float vv[4] = {stA[i].x, stA[i].y, stA[i].z, stA[i].w};
            #pragma unroll
            for (int j = 0; j < 4; j++)
                *reinterpret_cast<float2*>(&As2[buf][kq + j][2 * row]) =
                    make_float2(vv[j], vv[j]);
        }
        #pragma unroll
        for (int i = 0; i < CB; i++) {
            int f4 = tid + i * TH;
            int row = f4 >> 1, kq = (f4 & 1) << 2;
            Bs[buf][kq + 0][row] = stB[i].x;
            Bs[buf][kq + 1][row] = stB[i].y;
            Bs[buf][kq + 2][row] = stB[i].z;
            Bs[buf][kq + 3][row] = stB[i].w;
        }
    };

    const int nt = (K + BK - 1) / BK;
    ldGA(0); ldGB(0); stS(0);
    __syncthreads();

    for (int t = 0; t < nt; t++) {
        int buf = t & 1;
        if (t + 1 < nt) { ldGA((t + 1) * BK); ldGB((t + 1) * BK); }
        #pragma unroll
        for (int k = 0; k < BK; k++) {
            ulonglong2 a01 = *reinterpret_cast<const ulonglong2*>(&As2[buf][k][2 * (ty * 4)]);
            ulonglong2 a23 = *reinterpret_cast<const ulonglong2*>(&As2[buf][k][2 * (ty * 4) + 4]);
            ulonglong2 a45 = *reinterpret_cast<const ulonglong2*>(&As2[buf][k][2 * (BM / 2 + ty * 4)]);
            ulonglong2 a67 = *reinterpret_cast<const ulonglong2*>(&As2[buf][k][2 * (BM / 2 + ty * 4) + 4]);
            ulonglong2 b01 = *reinterpret_cast<const ulonglong2*>(&Bs[buf][k][tx * 4]);
            ulonglong2 b23 = *reinterpret_cast<const ulonglong2*>(&Bs[buf][k][BN / 2 + tx * 4]);
            unsigned long long av[8] = {a01.x, a01.y, a23.x, a23.y,
                                        a45.x, a45.y, a67.x, a67.y};
            unsigned long long bv[4] = {b01.x, b01.y, b23.x, b23.y};
            #pragma unroll
            for (int i = 0; i < 8; i++)
                #pragma unroll
                for (int j = 0; j < 4; j++)
                    FMA_F32X2(acc[i][j], av[i], bv[j], acc[i][j]);
        }
        if (t + 1 < nt) stS(buf ^ 1);
        __syncthreads();
    }

    #pragma unroll
    for (int i = 0; i < 8; i++) {
        int m = m0 + ((i < 4) ? (ty * 4 + i) : (BM / 2 + ty * 4 + i - 4));
        float4 o0, o1;
        o0.x = f2lo(acc[i][0]); o0.y = f2hi(acc[i][0]);
        o0.z = f2lo(acc[i][1]); o0.w = f2hi(acc[i][1]);
        o1.x = f2lo(acc[i][2]); o1.y = f2hi(acc[i][2]);
        o1.z = f2lo(acc[i][3]); o1.w = f2hi(acc[i][3]);
        *reinterpret_cast<float4*>(&C[(size_t)m * ldc + n0 + tx * 4]) = o0;
        *reinterpret_cast<float4*>(&C[(size_t)m * ldc + n0 + BN / 2 + tx * 4]) = o1;
    }
}

// ---------------------------------------------------------------------------
// Symmetric fp32 GEMM: C = X.X^T per batch (lower triangle + mirror store).
// Diagonal tiles also write xx[p] = C[p][p] (replaces diag_xx kernel;
// identical fp32 value -> bit-exact downstream keys).
// ---------------------------------------------------------------------------
__global__ void __launch_bounds__(256, 2)
gemm_sym(const float* __restrict__ X, int lda, long long sX,
         float* __restrict__ C, int ldc, long long sC, int K,
         float* __restrict__ xx)
{
    constexpr int BM = 128, BN = 128, BK = 8;
    constexpr int LA = 2 * BM + 4;
    constexpr int LB = BN + 4;
    constexpr int NX = BN / 8;

    __shared__ float As2[2][BK][LA];
    __shared__ float Bs[2][BK][LB];

    int t = blockIdx.x;
    int i_ = (int)((sqrtf(8.f * t + 1.f) - 1.f) * 0.5f);
    while ((i_ + 1) * (i_ + 2) / 2 <= t) i_++;
    while (i_ * (i_ + 1) / 2 > t) i_--;
    int j_ = t - i_ * (i_ + 1) / 2;

    const int bz = blockIdx.z;
    const float* A = X + bz * sX;
    float* Cb = C + bz * sC;
    const int m0 = i_ * BM;
    const int n0 = j_ * BN;
    const int tid = threadIdx.x;
    const int tx = tid % NX;
    const int ty = tid / NX;
    const bool a4 = ((lda & 3) == 0);

    unsigned long long acc[8][4];
    #pragma unroll
    for (int i = 0; i < 8; i++)
        #pragma unroll
        for (int j = 0; j < 4; j++) acc[i][j] = 0ull;

    float4 stA[1], stB[1];
    auto ldGA = [&](int k0) {
        int row = tid >> 1, kq = (tid & 1) << 2;
        int k = k0 + kq;
        const float* p = A + (size_t)(m0 + row) * lda;
        float4 v;
        if (a4 && (k + 3) < K) v = *reinterpret_cast<const float4*>(p + k);
        else {
            v.x = (k     < K) ? p[k]     : 0.f;
            v.y = (k + 1 < K) ? p[k + 1] : 0.f;
            v.z = (k + 2 < K) ? p[k + 2] : 0.f;
            v.w = (k + 3 < K) ? p[k + 3] : 0.f;
        }
        stA[0] = v;
    };
    auto ldGB = [&](int k0) {
        int row = tid >> 1, kq = (tid & 1) << 2;
        int k = k0 + kq;
        const float* p = A + (size_t)(n0 + row) * lda;
        float4 v;
        if (a4 && (k + 3) < K) v = *reinterpret_cast<const float4*>(p + k);
        else {
            v.x = (k     < K) ? p[k]     : 0.f;
            v.y = (k + 1 < K) ? p[k + 1] : 0.f;
            v.z = (k + 2 < K) ? p[k + 2] : 0.f;
            v.w = (k + 3 < K) ? p[k + 3] : 0.f;
        }
        stB[0] = v;
    };
    auto stS = [&](int buf) {
        int row = tid >> 1, kq = (tid & 1) << 2;
        float vv[4] = {stA[0].x, stA[0].y, stA[0].z, stA[0].w};
        #pragma unroll
        for (int j = 0; j < 4; j++)
            *reinterpret_cast<float2*>(&As2[buf][kq + j][2 * row]) =
                make_float2(vv[j], vv[j]);
        Bs[buf][kq + 0][row] = stB[0].x;
        Bs[buf][kq + 1][row] = stB[0].y;
        Bs[buf][kq + 2][row] = stB[0].z;
        Bs[buf][kq + 3][row] = stB[0].w;
    };

    const int nt = (K + BK - 1) / BK;
    ldGA(0); ldGB(0); stS(0);
    __syncthreads();

    for (int tt = 0; tt < nt; tt++) {
        int buf = tt & 1;
        if (tt + 1 < nt) { ldGA((tt + 1) * BK); ldGB((tt + 1) * BK); }
        #pragma unroll
        for (int k = 0; k < BK; k++) {
            ulonglong2 a01 = *reinterpret_cast<const ulonglong2*>(&As2[buf][k][2 * (ty * 4)]);
            ulonglong2 a23 = *reinterpret_cast<const ulonglong2*>(&As2[buf][k][2 * (ty * 4) + 4]);
            ulonglong2 a45 = *reinterpret_cast<const ulonglong2*>(&As2[buf][k][2 * (BM / 2 + ty * 4)]);
            ulonglong2 a67 = *reinterpret_cast<const ulonglong2*>(&As2[buf][k][2 * (BM / 2 + ty * 4) + 4]);
            ulonglong2 b01 = *reinterpret_cast<const ulonglong2*>(&Bs[buf][k][tx * 4]);
            ulonglong2 b23 = *reinterpret_cast<const ulonglong2*>(&Bs[buf][k][BN / 2 + tx * 4]);
            unsigned long long av[8] = {a01.x, a01.y, a23.x, a23.y,
                                        a45.x, a45.y, a67.x, a67.y};
            unsigned long long bv[4] = {b01.x, b01.y, b23.x, b23.y};
            #pragma unroll
            for (int i = 0; i < 8; i++)
                #pragma unroll
                for (int j = 0; j < 4; j++)
                    FMA_F32X2(acc[i][j], av[i], bv[j], acc[i][j]);
        }
        if (tt + 1 < nt) stS(buf ^ 1);
        __syncthreads();
    }

    float f[8][8];
    int mrow[8], ncol[8];
    #pragma unroll
    for (int i = 0; i < 8; i++) {
        mrow[i] = m0 + ((i < 4) ? (ty * 4 + i) : (64 + ty * 4 + i - 4));
        ncol[i] = n0 + ((i < 4) ? (tx * 4 + i) : (64 + tx * 4 + i - 4));
        f[i][0] = f2lo(acc[i][0]); f[i][1] = f2hi(acc[i][0]);
        f[i][2] = f2lo(acc[i][1]); f[i][3] = f2hi(acc[i][1]);
        f[i][4] = f2lo(acc[i][2]); f[i][5] = f2hi(acc[i][2]);
        f[i][6] = f2lo(acc[i][3]); f[i][7] = f2hi(acc[i][3]);
    }

    #pragma unroll
    for (int i = 0; i < 8; i++) {
        *reinterpret_cast<float4*>(&Cb[(size_t)mrow[i] * ldc + ncol[0]]) =
            make_float4(f[i][0], f[i][1], f[i][2], f[i][3]);
        *reinterpret_cast<float4*>(&Cb[(size_t)mrow[i] * ldc + ncol[4]]) =
            make_float4(f[i][4], f[i][5], f[i][6], f[i][7]);
    }
    if (i_ != j_) {
        #pragma unroll
        for (int q = 0; q < 8; q++) {
            *reinterpret_cast<float4*>(&Cb[(size_t)ncol[q] * ldc + mrow[0]]) =
                make_float4(f[0][q], f[1][q], f[2][q], f[3][q]);
            *reinterpret_cast<float4*>(&Cb[(size_t)ncol[q] * ldc + mrow[4]]) =
                make_float4(f[4][q], f[5][q], f[6][q], f[7][q]);
        }
    } else {
        // diagonal tile: owner thread emits xx[p] = C[p][p]
        #pragma unroll
        for (int i = 0; i < 8; i++) {
            int d   = mrow[i] - m0;                 // 0..127
            int loc = d & 63;
            if ((loc >> 2) == tx) {
                int q = ((d & 64) ? 4 : 0) + (loc & 3);
                xx[bz * N_ + mrow[i]] = f[i][q];
            }
        }
    }
}

// ---------------------------------------------------------------------------
// top-20: warp per row, float4 scan, u32 key top-2 cache + index regs,
// pops via redux.sync.max.u32 pair.
// ---------------------------------------------------------------------------
__device__ __forceinline__ void tk_upd(unsigned& k1, unsigned& m1,
                                       unsigned& k2, unsigned& m2,
                                       unsigned e, unsigned m) {
    if (e > k1)      { k2 = k1; m2 = m1; k1 = e; m1 = m; }
    else if (e > k2) { k2 = e; m2 = m; }
}

__global__ void __launch_bounds__(256)
topk_kernel(const float* __restrict__ inner, const float* __restrict__ xx,
            int* __restrict__ idx_out)
{
    __shared__ uint4 s4[8][N_ / 4];
    int wid  = threadIdx.x >> 5;
    int lane = threadIdx.x & 31;
    int row  = blockIdx.x * 8 + wid;
    int b    = row >> 10;
    uint4* sw4 = s4[wid];
    unsigned* sw = reinterpret_cast<unsigned*>(sw4);
    const float4* r4 = reinterpret_cast<const float4*>(inner + (size_t)row * N_);
    const float4* x4 = reinterpret_cast<const float4*>(xx + (b << 10));

    unsigned k1 = 0, m1 = 0, k2 = 0, m2 = 0;
    #pragma unroll
    for (int i = 0; i < 8; i++) {
        int q = i * 32 + lane;
        float4 rv = r4[q];
        float4 xv = x4[q];
        unsigned mb = (unsigned)q * 4;
        unsigned e0 = fenc(fmaf(2.f, rv.x, -xv.x));
        unsigned e1 = fenc(fmaf(2.f, rv.y, -xv.y));
        unsigned e2 = fenc(fmaf(2.f, rv.z, -xv.z));
        unsigned e3 = fenc(fmaf(2.f, rv.w, -xv.w));
        sw4[q] = make_uint4(e0, e1, e2, e3);
        tk_upd(k1, m1, k2, m2, e0, mb);
        tk_upd(k1, m1, k2, m2, e1, mb + 1);
        tk_upd(k1, m1, k2, m2, e2, mb + 2);
        tk_upd(k1, m1, k2, m2, e3, mb + 3);
    }
    __syncwarp();

    for (int it = 0; it < KNN; it++) {
        unsigned wkey = redux_max(k1);
        unsigned cand = (k1 == wkey) ? (1023u - m1) : 0u;
        unsigned widx = redux_max(cand);
        unsigned m = 1023u - widx;
        if (lane == 0) idx_out[row * KNN + it] = (int)m;
        if (k1 == wkey && (1023u - m1) == widx) {
            sw[m] = 0;
            k1 = k2; m1 = m2; k2 = 0; m2 = 0;
            if (k1 == 0) {
                #pragma unroll
                for (int i = 0; i < 8; i++) {
                    int q = i * 32 + lane;
                    uint4 v = sw4[q];
                    unsigned mb = (unsigned)q * 4;
                    tk_upd(k1, m1, k2, m2, v.x, mb);
                    tk_upd(k1, m1, k2, m2, v.y, mb + 1);
                    tk_upd(k1, m1, k2, m2, v.z, mb + 2);
                    tk_upd(k1, m1, k2, m2, v.w, mb + 3);
                }
            }
        }
        __syncwarp();
    }
}

// ---------------------------------------------------------------------------
__device__ __forceinline__ void split_store(float v, __nv_bfloat16* h, __nv_bfloat16* l,
                                            size_t i)
{
    __nv_bfloat16 hb = __float2bfloat16(v);
    h[i] = hb;
    l[i] = __float2bfloat16(v - __bfloat162float(hb));
}

__global__ void prep_w(const float* __restrict__ W, int C, int O,
                       const float* __restrict__ bias,
                       const float* __restrict__ bng, const float* __restrict__ bnb,
                       float* __restrict__ utw,
                       __nv_bfloat16* __restrict__ utwh, __nv_bfloat16* __restrict__ utwl,
                       float* __restrict__ tb)
{
    const float inv = 1.0f / sqrtf(1.00001f);
    int i = blockIdx.x * 256 + threadIdx.x;
    if (i < O * C) {
        int o = i / C, c = i - o * C;
        float s = bng[o] * inv;
        float wa = W[o * 2 * C + c];
        float wb = W[o * 2 * C + C + c];
        float vu = s * wa;
        float vt = s * (wb - wa);
        utw[(size_t)o * C + c] = vu;
        utw[(size_t)(O + o) * C + c] = vt;
        split_store(vu, utwh, utwl, (size_t)o * C + c);
        split_store(vt, utwh, utwl, (size_t)(O + o) * C + c);
    }
    if (i < O) {
        float s = bng[i] * inv;
        tb[i] = s * (bias ? bias[i] : 0.f) + bnb[i];
    }
}

__global__ void prep_c5(const float* __restrict__ W,
                        __nv_bfloat16* __restrict__ h, __nv_bfloat16* __restrict__ l)
{
    int i = blockIdx.x * 256 + threadIdx.x;
    if (i < 1024 * 512) split_store(W[i], h, l, i);
}

// ---------------------------------------------------------------------------
__global__ void gathermax(const float* __restrict__ ut, const float* __restrict__ tb,
                          const int* __restrict__ idx,
                          float* __restrict__ xc,
                          __nv_bfloat16* __restrict__ xch, __nv_bfloat16* __restrict__ xcl,
                          int colOff, int CO)
{
    __shared__ int sidx[16][KNN];
    int ty = threadIdx.y, tx = threadIdx.x;
    int p = blockIdx.x * blockDim.y + ty;
    int b = p >> 10;
    for (int k = tx; k < KNN; k += blockDim.x) sidx[ty][k] = idx[p * KNN + k];
    __syncthreads();

    int st = 2 * CO;
    float4 tv = *reinterpret_cast<const float4*>(ut + (size_t)p * st + CO + tx * 4);
    float4 bv = *reinterpret_cast<const float4*>(tb + tx * 4);
    tv.x += bv.x; tv.y += bv.y; tv.z += bv.z; tv.w += bv.w;

    float4 mx = make_float4(NEG_INF, NEG_INF, NEG_INF, NEG_INF);
    #pragma unroll 4
    for (int k = 0; k < KNN; k++) {
        int j = sidx[ty][k];
        float4 v = *reinterpret_cast<const float4*>(
            ut + (size_t)((b << 10) + j) * st + tx * 4);
        mx.x = fmaxf(mx.x, v.x + tv.x);
        mx.y = fmaxf(mx.y, v.y + tv.y);
        mx.z = fmaxf(mx.z, v.z + tv.z);
        mx.w = fmaxf(mx.w, v.w + tv.w);
    }
    mx.x = (mx.x >= 0.f) ? mx.x : 0.01f * mx.x;
    mx.y = (mx.y >= 0.f) ? mx.y : 0.01f * mx.y;
    mx.z = (mx.z >= 0.f) ? mx.z : 0.01f * mx.z;
    mx.w = (mx.w >= 0.f) ? mx.w : 0.01f * mx.w;

    size_t o = (size_t)p * 512 + colOff + tx * 4;
    *reinterpret_cast<float4*>(xc + o) = mx;

    float vals[4] = {mx.x, mx.y, mx.z, mx.w};
    __nv_bfloat16 hb[4], lb[4];
    #pragma unroll
    for (int i = 0; i < 4; i++) {
        hb[i] = __float2bfloat16(vals[i]);
        lb[i] = __float2bfloat16(vals[i] - __bfloat162float(hb[i]));
    }
    *reinterpret_cast<uint2*>(xch + o) = *reinterpret_cast<uint2*>(hb);
    *reinterpret_cast<uint2*>(xcl + o) = *reinterpret_cast<uint2*>(lb);
}

// ---------------------------------------------------------------------------
__global__ void zero_pool(unsigned* pool)
{
    int i = blockIdx.x * 256 + threadIdx.x;
    if (i < B_ * 1024) pool[i] = 0u;
}

__device__ __forceinline__ float dec_pool(unsigned u)
{
    return (u & 0x80000000u) ? __uint_as_float(u & 0x7fffffffu) : __uint_as_float(~u);
}

// ---------------------------------------------------------------------------
__global__ void mlp1(const unsigned* __restrict__ pool, const float* __restrict__ w,
                     const float* __restrict__ g6, const float* __restrict__ b6,
                     float* __restrict__ y1)
{
    int b = blockIdx.y;
    int j = blockIdx.x * 4 + threadIdx.y;
    int lane = threadIdx.x;
    float s = 0.f;
    for (int c = lane; c < 1024; c += 32)
        s += dec_pool(pool[b * 1024 + c]) * w[j * 1024 + c];
    #pragma unroll
    for (int off = 16; off; off >>= 1) s += __shfl_xor_sync(0xffffffffu, s, off);
    if (lane == 0) {
        float v = s * (g6[j] * (1.0f / sqrtf(1.00001f))) + b6[j];
        y1[b * 512 + j] = (v >= 0.f) ? v : 0.01f * v;
    }
}

__global__ void mlp2(const float* __restrict__ y1, const float* __restrict__ w,
                     const float* __restrict__ wb, const float* __restrict__ g7,
                     const float* __restrict__ b7, float* __restrict__ y2)
{
    int b = blockIdx.y;
    int j = blockIdx.x * 4 + threadIdx.y;
    int lane = threadIdx.x;
    float s = 0.f;
    for (int c = lane; c < 512; c += 32) s += y1[b * 512 + c] * w[j * 512 + c];
    #pragma unroll
    for (int off = 16; off; off >>= 1) s += __shfl_xor_sync(0xffffffffu, s, off);
    if (lane == 0) {
        float v = (s + wb[j]) * (g7[j] * (1.0f / sqrtf(1.00001f))) + b7[j];
        y2[b * 256 + j] = (v >= 0.f) ? v : 0.01f * v;
    }
}

__global__ void mlp3(const float* __restrict__ y2, const float* __restrict__ w,
                     const float* __restrict__ wb, float* __restrict__ out)
{
    int b = blockIdx.y;
    int j = blockIdx.x * 4 + threadIdx.y;
    int lane = threadIdx.x;
    float s = 0.f;
    for (int c = lane; c < 256; c += 32) s += y2[b * 256 + c] * w[j * 256 + c];
    #pragma unroll
    for (int off = 16; off; off >>= 1) s += __shfl_xor_sync(0xffffffffu, s, off);
    if (lane == 0) out[b * 40 + j] = s + wb[j];
}

// ---------------------------------------------------------------------------
extern "C" void kernel_launch(void* const* d_in, const int* in_sizes, int n_in,
                              void* d_out, int out_size)
{
    const float* x        = (const float*)d_in[0];
    const float* conv1_w  = (const float*)d_in[1];
    const float* conv1_b  = (const float*)d_in[2];
    const float* bn1_g    = (const float*)d_in[3];
    const float* bn1_b    = (const float*)d_in[4];
    const float* conv2_w  = (const float*)d_in[5];
    const float* bn2_g    = (const float*)d_in[6];
    const float* bn2_b    = (const float*)d_in[7];
    const float* conv3_w  = (const float*)d_in[8];
    const float* bn3_g    = (const float*)d_in[9];
    const float* bn3_b    = (const float*)d_in[10];
    const float* conv4_w  = (const float*)d_in[11];
    const float* bn4_g    = (const float*)d_in[12];
    const float* bn4_b    = (const float*)d_in[13];
    const float* conv5_w  = (const float*)d_in[14];
    const float* lin1_w   = (const float*)d_in[15];
    const float* bn6_g    = (const float*)d_in[16];
    const float* bn6_b    = (const float*)d_in[17];
    const float* lin2_w   = (const float*)d_in[18];
    const float* lin2_b   = (const float*)d_in[19];
    const float* bn7_g    = (const float*)d_in[20];
    const float* bn7_b    = (const float*)d_in[21];
    const float* lin3_w   = (const float*)d_in[22];
    const float* lin3_b   = (const float*)d_in[23];

    float *xc, *inner, *ut, *utw, *tb, *xxp, *y1, *y2;
    __nv_bfloat16 *xch, *xcl, *utwh, *utwl, *c5h, *c5l;
    int* idx; unsigned* pool;
    cudaGetSymbolAddress((void**)&xc,    g_xc);
    cudaGetSymbolAddress((void**)&inner, g_inner);
    cudaGetSymbolAddress((void**)&xch,   g_xch);
    cudaGetSymbolAddress((void**)&xcl,   g_xcl);
    cudaGetSymbolAddress((void**)&ut,    g_ut);
    cudaGetSymbolAddress((void**)&utw,   g_utw);
    cudaGetSymbolAddress((void**)&utwh,  g_utwh);
    cudaGetSymbolAddress((void**)&utwl,  g_utwl);
    cudaGetSymbolAddress((void**)&c5h,   g_c5h);
    cudaGetSymbolAddress((void**)&c5l,   g_c5l);
    cudaGetSymbolAddress((void**)&tb,    g_tb);
    cudaGetSymbolAddress((void**)&xxp,   g_xx);
    cudaGetSymbolAddress((void**)&idx,   g_idx);
    cudaGetSymbolAddress((void**)&pool,  g_pool);
    cudaGetSymbolAddress((void**)&y1,    g_y1);
    cudaGetSymbolAddress((void**)&y2,    g_y2);

    cudaFuncSetAttribute(mma_gemm, cudaFuncAttributeMaxDynamicSharedMemorySize, MMA_SMEM);
    cudaFuncSetAttribute(mma_gemm_pool, cudaFuncAttributeMaxDynamicSharedMemorySize,
                         MMA_SMEM_POOL);

    static cudaStream_t s2 = nullptr;
    static cudaEvent_t evf[4], evj[4];
    if (s2 == nullptr) {
        cudaStreamCreateWithFlags(&s2, cudaStreamNonBlocking);
        for (int i = 0; i < 4; i++) {
            cudaEventCreateWithFlags(&evf[i], cudaEventDisableTiming);
            cudaEventCreateWithFlags(&evj[i], cudaEventDisableTiming);
        }
    }

    struct Layer {
        int inOff; int Cin; int Cout; int outOff;
        const float* W; const float* bias; const float* g; const float* bb;
    };
    Layer L[4] = {
        { -1,  3,   64,  0,   conv1_w, conv1_b, bn1_g, bn1_b },
        { 0,   64,  64,  64,  conv2_w, nullptr, bn2_g, bn2_b },
        { 64,  64,  128, 128, conv3_w, nullptr, bn3_g, bn3_b },
        { 128, 128, 256, 256, conv4_w, nullptr, bn4_g, bn4_b },
    };

    zero_pool<<<32, 256>>>(pool);

    for (int l = 0; l < 4; l++) {
        const Layer& a = L[l];
        const float* fin = (l == 0) ? x : (xc + a.inOff);
        int lda = (l == 0) ? 3 : 512;

        // fork: side stream computes the thin [prep -> u|t GEMM] chain
        cudaEventRecord(evf[l], 0);
        cudaStreamWaitEvent(s2, evf[l], 0);

        if (l == 0)
            prep_c5<<<(1024 * 512 + 255) / 256, 256, 0, s2>>>(conv5_w, c5h, c5l);
        prep_w<<<(a.Cout * a.Cin + 255) / 256, 256, 0, s2>>>(
            a.W, a.Cin, a.Cout, a.bias, a.g, a.bb, utw, utwh, utwl, tb);
        if (l == 0) {
            gemm_f2<128, 64, 128><<<dim3(2, PTS / 128, 1), 128, 0, s2>>>(
                x, 3, 0, utw, 3, 0, ut, 128, 0, 3);
        } else {
            mma_gemm<<<dim3(2 * a.Cout / 128, PTS / 128, 1), 256, MMA_SMEM, s2>>>(
                xch + a.inOff, xcl + a.inOff, 512, 0,
                utwh, utwl, a.Cin, 0,
                ut, 2 * a.Cout, 0, a.Cin);
        }
        cudaEventRecord(evj[l], s2);

        // main stream: KNN chain (xx emitted by gemm_sym diagonal tiles)
        gemm_sym<<<dim3(36, 1, B_), 256>>>(
            fin, lda, (long long)N_ * lda, inner, N_, (long long)N_ * N_,
            a.Cin, xxp);
        topk_kernel<<<PTS / 8, 256>>>(inner, xxp, idx);

        // join, then gather
        cudaStreamWaitEvent(0, evj[l], 0);
        int cx = a.Cout / 4;
        int ppb = 1024 / a.Cout;
        if (ppb > 16) ppb = 16;
        gathermax<<<PTS / ppb, dim3(cx, ppb)>>>(ut, tb, idx, xc, xch, xcl,
                                                a.outOff, a.Cout);
    }

    // conv5 fused with global max-pool
    mma_gemm_pool<<<dim3(8, PTS / 128, 1), 256, MMA_SMEM_POOL>>>(
        xch, xcl, 512, c5h, c5l, 512, pool, 512);

    // MLP head (separate wide-grid kernels: weight reads spread over many CTAs)
    mlp1<<<dim3(128, B_), dim3(32, 4)>>>(pool, lin1_w, bn6_g, bn6_b, y1);
    mlp2<<<dim3(64, B_),  dim3(32, 4)>>>(y1, lin2_w, lin2_b, bn7_g, bn7_b, y2);
    mlp3<<<dim3(10, B_),  dim3(32, 4)>>>(y2, lin3_w, lin3_b, (float*)d_out);
}